// round 14
// baseline (speedup 1.0000x reference)
#include <cuda_runtime.h>
#include <cuda_bf16.h>
#include <cstdint>
#include <cstddef>

// ---------------------------------------------------------------------------
// MambaSequenceClassifier: B=8, L=1024, D_MODEL=256, D_INNER=512, D_STATE=16,
// D_CONV=4, DT_RANK=16, N_LAYERS=2.
// Round 14: scan1/scan2 software-pipelined loads (prefetch t+1 while computing
// t), combine_k fully unrolled for load batching.  Conv MLP fix retained.
// ---------------------------------------------------------------------------

#define B_SZ    8
#define L_SZ    1024
#define DM      256
#define DI      512
#define DS      16
#define DCNV    4
#define DR      16
#define NT      (B_SZ * L_SZ)        // 8192 tokens
#define NCHUNK  32
#define CLEN    (L_SZ / NCHUNK)      // 32
#define EPSF    1e-5f
#define PITCH   80
#define CTT     16                   // conv timesteps per thread

__device__ __forceinline__ uint32_t smem_to_u32(const void* p) {
    uint32_t a;
    asm("{ .reg .u64 t; cvta.to.shared.u64 t, %1; cvt.u32.u64 %0, t; }"
        : "=r"(a) : "l"(p));
    return a;
}
__device__ __forceinline__ void ldsm_x4(uint32_t (&r)[4], uint32_t addr) {
    asm volatile("ldmatrix.sync.aligned.m8n8.x4.shared.b16 {%0,%1,%2,%3}, [%4];"
        : "=r"(r[0]), "=r"(r[1]), "=r"(r[2]), "=r"(r[3]) : "r"(addr));
}
__device__ __forceinline__ void mma_bf16(float (&d)[4], const uint32_t (&a)[4],
                                         uint32_t b0, uint32_t b1) {
    asm volatile("mma.sync.aligned.m16n8k16.row.col.f32.bf16.bf16.f32 "
        "{%0,%1,%2,%3},{%4,%5,%6,%7},{%8,%9},{%0,%1,%2,%3};"
        : "+f"(d[0]), "+f"(d[1]), "+f"(d[2]), "+f"(d[3])
        : "r"(a[0]), "r"(a[1]), "r"(a[2]), "r"(a[3]), "r"(b0), "r"(b1));
}
__device__ __forceinline__ void cp_async16(uint32_t saddr, const void* gptr) {
    asm volatile("cp.async.cg.shared.global [%0], [%1], 16;"
        :: "r"(saddr), "l"(gptr));
}
#define CP_COMMIT() asm volatile("cp.async.commit_group;" ::: "memory")
template<int N>
__device__ __forceinline__ void cp_wait() {
    asm volatile("cp.async.wait_group %0;" :: "n"(N) : "memory");
}
__device__ __forceinline__ void split2(float x, __nv_bfloat16& hi, __nv_bfloat16& lo)
{
    hi = __float2bfloat16(x);
    lo = __float2bfloat16(x - __bfloat162float(hi));
}

// ---------------- device scratch (no allocation allowed) -------------------
__device__ float g_X    [NT * DM];
__device__ float g_XZ   [NT * 2 * DI];
__device__ float g_DBC  [NT * 64];
__device__ float g_DELTA[NT * DI];
__device__ float g_HC   [B_SZ * NCHUNK * DI * DS];
__device__ float g_PC   [B_SZ * NCHUNK * DI * DS];
__device__ float g_HIN  [B_SZ * NCHUNK * DI * DS];
__device__ float g_PX   [4 * NT * 64];
__device__ float g_PO   [2 * NT * DM];
__device__ float g_YGF  [B_SZ * DI];

__device__ __nv_bfloat16 g_XNh[NT * DM],  g_XNl[NT * DM];
__device__ __nv_bfloat16 g_XIh[NT * DI],  g_XIl[NT * DI];
__device__ __nv_bfloat16 g_YGh[NT * DI],  g_YGl[NT * DI];
__device__ __nv_bfloat16 g_Wih[2 * 1024 * DM], g_Wil[2 * 1024 * DM];
__device__ __nv_bfloat16 g_Wxh[2 * 64 * DI],   g_Wxl[2 * 64 * DI];
__device__ __nv_bfloat16 g_Woh[DM * DI],       g_Wol[DM * DI];

// ---------------------------------------------------------------------------
__global__ void repack_k(const float* __restrict__ W, __nv_bfloat16* __restrict__ Bh,
                         __nv_bfloat16* __restrict__ Bl, int K, int Norig,
                         size_t wstride, size_t bstride)
{
    __shared__ float t[64][65];
    int l = blockIdx.z;
    W  += (size_t)l * wstride;
    Bh += (size_t)l * bstride;
    Bl += (size_t)l * bstride;
    int k0 = blockIdx.x * 64, n0 = blockIdx.y * 64;
    int ty = threadIdx.x >> 6, tx = threadIdx.x & 63;

#pragma unroll
    for (int p = 0; p < 16; p++) {
        int k = k0 + p * 4 + ty;
        int n = n0 + tx;
        float v = (n < Norig) ? W[(size_t)k * Norig + n] : 0.f;
        t[tx][p * 4 + ty] = v;
    }
    __syncthreads();
#pragma unroll
    for (int p = 0; p < 16; p++) {
        int n = n0 + p * 4 + ty;
        int k = k0 + tx;
        float v = t[p * 4 + ty][tx];
        __nv_bfloat16 hi, lo;
        split2(v, hi, lo);
        Bh[(size_t)n * K + k] = hi;
        Bl[(size_t)n * K + k] = lo;
    }
}

// ---------------------------------------------------------------------------
__global__ void rmsnorm_k(const float* __restrict__ X, const float* __restrict__ w,
                          __nv_bfloat16* __restrict__ XNh, __nv_bfloat16* __restrict__ XNl)
{
    int warp = threadIdx.x >> 5, lane = threadIdx.x & 31;
    size_t row = (size_t)blockIdx.x * 8 + warp;
    const float* xr = X + row * DM;
    float v[8];
    float ss = 0.f;
#pragma unroll
    for (int i = 0; i < 8; i++) { v[i] = xr[lane + 32 * i]; ss += v[i] * v[i]; }
#pragma unroll
    for (int o = 16; o; o >>= 1) ss += __shfl_xor_sync(0xffffffffu, ss, o);
    float rs = rsqrtf(ss * (1.f / DM) + EPSF);
#pragma unroll
    for (int i = 0; i < 8; i++) {
        int j = lane + 32 * i;
        float y = v[i] * rs * w[j];
        __nv_bfloat16 hi, lo;
        split2(y, hi, lo);
        XNh[row * DM + j] = hi; XNl[row * DM + j] = lo;
    }
}

// ---------------------------------------------------------------------------
template<int BM, int BN>
__global__ void __launch_bounds__(256)
mma_gemm_k(const __nv_bfloat16* __restrict__ Ah, const __nv_bfloat16* __restrict__ Al,
           const __nv_bfloat16* __restrict__ Bh, const __nv_bfloat16* __restrict__ Bl,
           float* __restrict__ C, int Ktot, int klen, int ldc)
{
    constexpr int WM   = (BM == 128) ? 2 : 4;
    constexpr int WN   = 8 / WM;
    constexpr int MT   = BM / WM;
    constexpr int NTT  = BN / WN;
    constexpr int MT16 = MT / 16;
    constexpr int NP   = NTT / 16;
    constexpr int ABY  = BM * PITCH;
    constexpr int BBY  = BN * PITCH;
    constexpr int QA   = (BM * 4) / 256;
    constexpr int QB   = (BN * 4) / 256;

    __shared__ __align__(16) char sm[2][ABY + BBY];

    const int tid = threadIdx.x, wid = tid >> 5, lane = tid & 31;
    const int wm = wid % WM, wn = wid / WM;
    const int bn = blockIdx.x, bm = blockIdx.y;
    const int k0 = blockIdx.z * klen;
    const int zrow = blockIdx.z * gridDim.y * BM;

    uint32_t sA[2], sB[2];
#pragma unroll
    for (int s = 0; s < 2; s++) {
        sA[s] = smem_to_u32(sm[s]);
        sB[s] = sA[s] + ABY;
    }

    float acc[MT16][4][4];
#pragma unroll
    for (int i = 0; i < MT16; i++)
#pragma unroll
        for (int j = 0; j < 4; j++)
#pragma unroll
            for (int q = 0; q < 4; q++) acc[i][j][q] = 0.f;

    const int a_row = lane & 15;
    const int a_seg = lane >> 4;
    const int b_row = ((lane >> 4) << 3) | (lane & 7);
    const int b_seg = (lane >> 3) & 1;

    const int KC  = klen / 32;
    const int nkc = 3 * KC;

    auto issue = [&](int stage, int kc) {
        const int pl   = kc / KC;
        const int kcol = k0 + (kc - pl * KC) * 32;
        const __nv_bfloat16* Ap = (pl == 2) ? Al : Ah;
        const __nv_bfloat16* Bp = (pl == 1) ? Bl : Bh;
#pragma unroll
        for (int q = 0; q < QA; q++) {
            int f = tid + q * 256, r = f >> 2, s = f & 3;
            cp_async16(sA[stage] + r * PITCH + s * 16,
                       Ap + (size_t)(bm * BM + r) * Ktot + kcol + s * 8);
        }
#pragma unroll
        for (int q = 0; q < QB; q++) {
            int f = tid + q * 256, r = f >> 2, s = f & 3;
            cp_async16(sB[stage] + r * PITCH + s * 16,
                       Bp + (size_t)(bn * BN + r) * Ktot + kcol + s * 8);
        }
    };

    issue(0, 0);
    CP_COMMIT();

    for (int kc = 0; kc < nkc; kc++) {
        const int buf = kc & 1;
        if (kc + 1 < nkc) {
            issue(buf ^ 1, kc + 1);
            CP_COMMIT();
            cp_wait<1>();
        } else {
            cp_wait<0>();
        }
        __syncthreads();

#pragma unroll
        for (int k16 = 0; k16 < 2; k16++) {
            uint32_t afr[MT16][4], bfr[NP][4];
#pragma unroll
            for (int mt = 0; mt < MT16; mt++) {
                int row = wm * MT + mt * 16 + a_row;
                ldsm_x4(afr[mt], sA[buf] + row * PITCH + (k16 * 2 + a_seg) * 16);
            }
#pragma unroll
            for (int np = 0; np < NP; np++) {
                int row = wn * NTT + np * 16 + b_row;
                ldsm_x4(bfr[np], sB[buf] + row * PITCH + (k16 * 2 + b_seg) * 16);
            }
#pragma unroll
            for (int mt = 0; mt < MT16; mt++)
#pragma unroll
                for (int np = 0; np < NP; np++) {
                    mma_bf16(acc[mt][2 * np + 0], afr[mt], bfr[np][0], bfr[np][1]);
                    mma_bf16(acc[mt][2 * np + 1], afr[mt], bfr[np][2], bfr[np][3]);
                }
        }
        __syncthreads();
    }

    const int r0 = zrow + bm * BM + wm * MT + (lane >> 2);
    const int c0 = bn * BN + wn * NTT + (lane & 3) * 2;
#pragma unroll
    for (int mt = 0; mt < MT16; mt++) {
#pragma unroll
        for (int nt = 0; nt < 4; nt++) {
            int row = r0 + mt * 16;
            int col = c0 + nt * 8;
            *(float2*)(C + (size_t)row * ldc + col) =
                make_float2(acc[mt][nt][0], acc[mt][nt][1]);
            *(float2*)(C + (size_t)(row + 8) * ldc + col) =
                make_float2(acc[mt][nt][2], acc[mt][nt][3]);
        }
    }
}

// ---------------------------------------------------------------------------
__global__ void reduce2_resid_k(const float* __restrict__ P,
                                const float* __restrict__ xin,
                                float* __restrict__ X, int n4)
{
    int i = blockIdx.x * 256 + threadIdx.x;
    const float4* p = (const float4*)P;
    float4 a = p[i], b = p[i + n4];
    float4 xv = ((const float4*)xin)[i];
    xv.x += a.x + b.x;
    xv.y += a.y + b.y;
    xv.z += a.z + b.z;
    xv.w += a.w + b.w;
    ((float4*)X)[i] = xv;
}

// ---------------------------------------------------------------------------
__global__ void __launch_bounds__(256)
delta_fused_k(const float* __restrict__ PX, const float* __restrict__ dtw,
              const float* __restrict__ dtb, float* __restrict__ DBC,
              float* __restrict__ DELTA)
{
    __shared__ float sr[64][DR];
    const int tid = threadIdx.x;
    const size_t m0 = (size_t)blockIdx.x * 64;
    const int n4tot = NT * 16;

#pragma unroll
    for (int q = 0; q < 4; q++) {
        int f = tid + q * 256;
        int t = f >> 4, c4 = (f & 15);
        size_t o = (m0 + t) * 16 + c4;
        const float4* p = (const float4*)PX;
        float4 a = p[o], b = p[o + n4tot], c = p[o + 2 * n4tot], d = p[o + 3 * n4tot];
        float4 r;
        r.x = (a.x + b.x) + (c.x + d.x);
        r.y = (a.y + b.y) + (c.y + d.y);
        r.z = (a.z + b.z) + (c.z + d.z);
        r.w = (a.w + b.w) + (c.w + d.w);
        ((float4*)DBC)[o] = r;
        if (c4 < 4) *(float4*)(&sr[t][c4 * 4]) = r;
    }
    __syncthreads();

    int d0 = tid, d1 = tid + 256;
    float wt0[DR], wt1[DR];
#pragma unroll
    for (int r = 0; r < DR; r++) {
        wt0[r] = dtw[r * DI + d0];
        wt1[r] = dtw[r * DI + d1];
    }
    float b0 = dtb[d0], b1 = dtb[d1];

    for (int t = 0; t < 64; t++) {
        float a0 = b0, a1 = b1;
#pragma unroll
        for (int r = 0; r < DR; r++) {
            float s = sr[t][r];
            a0 += s * wt0[r];
            a1 += s * wt1[r];
        }
        float sp0 = fmaxf(a0, 0.f) + __logf(1.f + __expf(-fabsf(a0)));
        float sp1 = fmaxf(a1, 0.f) + __logf(1.f + __expf(-fabsf(a1)));
        DELTA[(m0 + t) * DI + d0] = sp0;
        DELTA[(m0 + t) * DI + d1] = sp1;
    }
}

// ---------------------------------------------------------------------------
// causal depthwise conv (width 4) + bias + silu -> bf16 hi/lo (MLP tiled)
// ---------------------------------------------------------------------------
__global__ void __launch_bounds__(128)
conv_silu_k(const float* __restrict__ XZ, const float* __restrict__ cw,
            const float* __restrict__ cb,
            __nv_bfloat16* __restrict__ XIh, __nv_bfloat16* __restrict__ XIl)
{
    int d  = blockIdx.x * 128 + threadIdx.x;
    int b  = blockIdx.z;
    int t0 = blockIdx.y * CTT;

    float w0 = cw[d * 4 + 0], w1 = cw[d * 4 + 1];
    float w2 = cw[d * 4 + 2], w3 = cw[d * 4 + 3];
    float bias = cb[d];

    const float* base = XZ + (size_t)b * L_SZ * (2 * DI) + d;

    float v[CTT + 3];
    v[0] = (t0 - 3 >= 0) ? base[(size_t)(t0 - 3) * (2 * DI)] : 0.f;
    v[1] = (t0 - 2 >= 0) ? base[(size_t)(t0 - 2) * (2 * DI)] : 0.f;
    v[2] = (t0 - 1 >= 0) ? base[(size_t)(t0 - 1) * (2 * DI)] : 0.f;
#pragma unroll
    for (int i = 0; i < CTT; i++)
        v[i + 3] = base[(size_t)(t0 + i) * (2 * DI)];

    size_t o = ((size_t)b * L_SZ + t0) * DI + d;
#pragma unroll
    for (int i = 0; i < CTT; i++) {
        float y = w0 * v[i] + w1 * v[i + 1] + w2 * v[i + 2] + w3 * v[i + 3] + bias;
        y = y / (1.f + __expf(-y));
        __nv_bfloat16 hi, lo;
        split2(y, hi, lo);
        XIh[o + (size_t)i * DI] = hi;
        XIl[o + (size_t)i * DI] = lo;
    }
}

// ---------------------------------------------------------------------------
// scan pass 1, software-pipelined loads (prefetch t+1 while computing t).
// ---------------------------------------------------------------------------
__global__ void __launch_bounds__(128)
scan1_k(const float* __restrict__ DELTA,
        const __nv_bfloat16* __restrict__ XIh, const __nv_bfloat16* __restrict__ XIl,
        const float* __restrict__ DBC, const float* __restrict__ alog,
        float* __restrict__ HC, float* __restrict__ PC)
{
    __shared__ float sB[CLEN][DS];
    int d = blockIdx.x * 128 + threadIdx.x;
    int c = blockIdx.y, b = blockIdx.z;
    size_t m0 = (size_t)b * L_SZ + (size_t)c * CLEN;

    for (int j = threadIdx.x; j < CLEN * DS; j += 128) {
        int i = j >> 4, n = j & 15;
        sB[i][n] = DBC[(m0 + i) * 64 + 16 + n];
    }

    float an[DS];
#pragma unroll
    for (int n = 0; n < DS; n++) an[n] = -__expf(alog[(size_t)d * DS + n]);
    float a0 = an[0];
    bool fast = true;
#pragma unroll
    for (int n = 1; n < DS; n++)
        if (fabsf(an[n] - a0 * (n + 1)) > 1e-4f * fabsf(an[n])) fast = false;
    __syncthreads();

    float h[DS], p[DS];
#pragma unroll
    for (int n = 0; n < DS; n++) { h[n] = 0.f; p[n] = 1.f; }

    const float* dp = DELTA + m0 * DI + d;
    const __nv_bfloat16* uph = XIh + m0 * DI + d;
    const __nv_bfloat16* upl = XIl + m0 * DI + d;

    // prologue loads for t=0
    float dl_c = dp[0];
    float uh_c = __bfloat162float(uph[0]);
    float ul_c = __bfloat162float(upl[0]);

    if (fast) {
        float sdl = 0.f;
#pragma unroll 4
        for (int t = 0; t < CLEN; t++) {
            float dl_n, uh_n, ul_n;
            if (t + 1 < CLEN) {
                dl_n = dp[(size_t)(t + 1) * DI];
                uh_n = __bfloat162float(uph[(size_t)(t + 1) * DI]);
                ul_n = __bfloat162float(upl[(size_t)(t + 1) * DI]);
            }
            float du = dl_c * (uh_c + ul_c);
            sdl += dl_c;
            float e1 = __expf(dl_c * a0);
            float pw[DS];
            pw[0] = e1;
            pw[1] = e1 * e1;
            pw[2] = pw[1] * e1;
            pw[3] = pw[1] * pw[1];
#pragma unroll
            for (int n = 4; n < DS; n++) pw[n] = pw[n - 4] * pw[3];
#pragma unroll
            for (int n = 0; n < DS; n++)
                h[n] = pw[n] * h[n] + du * sB[t][n];
            if (t + 1 < CLEN) { dl_c = dl_n; uh_c = uh_n; ul_c = ul_n; }
        }
        float es = __expf(a0 * sdl);
        p[0] = es;
        p[1] = es * es;
        p[2] = p[1] * es;
        p[3] = p[1] * p[1];
#pragma unroll
        for (int n = 4; n < DS; n++) p[n] = p[n - 4] * p[3];
    } else {
#pragma unroll 4
        for (int t = 0; t < CLEN; t++) {
            float dl_n, uh_n, ul_n;
            if (t + 1 < CLEN) {
                dl_n = dp[(size_t)(t + 1) * DI];
                uh_n = __bfloat162float(uph[(size_t)(t + 1) * DI]);
                ul_n = __bfloat162float(upl[(size_t)(t + 1) * DI]);
            }
            float du = dl_c * (uh_c + ul_c);
#pragma unroll
            for (int n = 0; n < DS; n++) {
                float dA = __expf(dl_c * an[n]);
                h[n] = dA * h[n] + du * sB[t][n];
                p[n] *= dA;
            }
            if (t + 1 < CLEN) { dl_c = dl_n; uh_c = uh_n; ul_c = ul_n; }
        }
    }

    size_t o = (((size_t)b * NCHUNK + c) * DI + d) * DS;
#pragma unroll
    for (int n = 0; n < DS; n++) { HC[o + n] = h[n]; PC[o + n] = p[n]; }
}

// fully unrolled so the compiler can front-batch loads across chunks
__global__ void __launch_bounds__(256)
combine_k(const float* __restrict__ HC, const float* __restrict__ PC,
          float* __restrict__ HIN)
{
    int b = blockIdx.y;
    int idx = blockIdx.x * 256 + threadIdx.x;
    float hin = 0.f;
#pragma unroll
    for (int c = 0; c < NCHUNK; c++) {
        size_t o = ((size_t)b * NCHUNK + c) * (DI * DS) + idx;
        float pc = PC[o], hc = HC[o];
        HIN[o] = hin;
        hin = pc * hin + hc;
    }
}

// ---------------------------------------------------------------------------
// scan pass 2 + gating, software-pipelined loads.
// ---------------------------------------------------------------------------
template<bool LAST_ONLY>
__global__ void __launch_bounds__(128)
scan2_k(const float* __restrict__ DELTA,
        const __nv_bfloat16* __restrict__ XIh, const __nv_bfloat16* __restrict__ XIl,
        const float* __restrict__ DBC, const float* __restrict__ alog,
        const float* __restrict__ dsk, const float* __restrict__ HIN,
        const float* __restrict__ XZ,
        __nv_bfloat16* __restrict__ YGh, __nv_bfloat16* __restrict__ YGl,
        float* __restrict__ YGF)
{
    __shared__ float sB[CLEN][DS];
    __shared__ float sC[CLEN][DS];
    int d = blockIdx.x * 128 + threadIdx.x;
    int c = LAST_ONLY ? (NCHUNK - 1) : blockIdx.y;
    int b = blockIdx.z;
    size_t m0 = (size_t)b * L_SZ + (size_t)c * CLEN;

    for (int j = threadIdx.x; j < CLEN * DS; j += 128) {
        int i = j >> 4, n = j & 15;
        sB[i][n] = DBC[(m0 + i) * 64 + 16 + n];
        sC[i][n] = DBC[(m0 + i) * 64 + 32 + n];
    }

    float an[DS];
#pragma unroll
    for (int n = 0; n < DS; n++) an[n] = -__expf(alog[(size_t)d * DS + n]);
    float a0 = an[0];
    bool fast = true;
#pragma unroll
    for (int n = 1; n < DS; n++)
        if (fabsf(an[n] - a0 * (n + 1)) > 1e-4f * fabsf(an[n])) fast = false;
    __syncthreads();

    float h[DS];
    size_t o = (((size_t)b * NCHUNK + c) * DI + d) * DS;
#pragma unroll
    for (int n = 0; n < DS; n++) h[n] = HIN[o + n];

    float Dd = dsk[d];
    const float* dp = DELTA + m0 * DI + d;
    const __nv_bfloat16* uph = XIh + m0 * DI + d;
    const __nv_bfloat16* upl = XIl + m0 * DI + d;
    const float* zp = XZ + m0 * (2 * DI) + DI + d;

    float dl_c = dp[0];
    float uh_c = __bfloat162float(uph[0]);
    float ul_c = __bfloat162float(upl[0]);
    float z_c  = zp[0];

#pragma unroll 4
    for (int t = 0; t < CLEN; t++) {
        float dl_n, uh_n, ul_n, z_n;
        if (t + 1 < CLEN) {
            dl_n = dp[(size_t)(t + 1) * DI];
            uh_n = __bfloat162float(uph[(size_t)(t + 1) * DI]);
            ul_n = __bfloat162float(upl[(size_t)(t + 1) * DI]);
            z_n  = zp[(size_t)(t + 1) * (2 * DI)];
        }
        float u  = uh_c + ul_c;
        float du = dl_c * u;
        float y0 = 0.f, y1 = 0.f, y2 = 0.f, y3 = 0.f;
        bool emit = !LAST_ONLY || (t == CLEN - 1);
        if (fast) {
            float e1 = __expf(dl_c * a0);
            float pw[DS];
            pw[0] = e1;
            pw[1] = e1 * e1;
            pw[2] = pw[1] * e1;
            pw[3] = pw[1] * pw[1];
#pragma unroll
            for (int n = 4; n < DS; n++) pw[n] = pw[n - 4] * pw[3];
#pragma unroll
            for (int n = 0; n < DS; n += 4) {
                h[n + 0] = pw[n + 0] * h[n + 0] + du * sB[t][n + 0];
                h[n + 1] = pw[n + 1] * h[n + 1] + du * sB[t][n + 1];
                h[n + 2] = pw[n + 2] * h[n + 2] + du * sB[t][n + 2];
                h[n + 3] = pw[n + 3] * h[n + 3] + du * sB[t][n + 3];
                y0 += h[n + 0] * sC[t][n + 0];
                y1 += h[n + 1] * sC[t][n + 1];
                y2 += h[n + 2] * sC[t][n + 2];
                y3 += h[n + 3] * sC[t][n + 3];
            }
        } else {
#pragma unroll
            for (int n = 0; n < DS; n++) {
                float dA = __expf(dl_c * an[n]);
                h[n] = dA * h[n] + du * sB[t][n];
                y0 += h[n] * sC[t][n];
            }
        }
        if (emit) {
            float y = (y0 + y1) + (y2 + y3);
            float g = z_c / (1.f + __expf(-z_c));
            float out = (y + u * Dd) * g;
            if (LAST_ONLY) {
                YGF[(size_t)b * DI + d] = out;
            } else {
                __nv_bfloat16 hi, lo;
                split2(out, hi, lo);
                YGh[m0 * DI + (size_t)t * DI + d] = hi;
                YGl[m0 * DI + (size_t)t * DI + d] = lo;
            }
        }
        if (t + 1 < CLEN) { dl_c = dl_n; uh_c = uh_n; ul_c = ul_n; z_c = z_n; }
    }
}

// ---------------------------------------------------------------------------
__global__ void __launch_bounds__(256)
final2_k(const float* __restrict__ X, const float* __restrict__ YGF,
         const float* __restrict__ opw1,
         const float* __restrict__ nfw, const float* __restrict__ fcw,
         const float* __restrict__ fcb, float* __restrict__ out)
{
    __shared__ float yg[DI];
    __shared__ float red[8];
    int b = blockIdx.x, n = threadIdx.x;
    int warp = n >> 5, lane = n & 31;

    for (int k = n; k < DI; k += 256) yg[k] = YGF[(size_t)b * DI + k];
    __syncthreads();

    float acc = 0.f;
#pragma unroll 4
    for (int k = 0; k < DI; k++)
        acc += yg[k] * opw1[(size_t)k * DM + n];

    float row = X[((size_t)b * L_SZ + (L_SZ - 1)) * DM + n] + acc;

    float ss = row * row;
#pragma unroll
    for (int o = 16; o; o >>= 1) ss += __shfl_xor_sync(0xffffffffu, ss, o);
    if (lane == 0) red[warp] = ss;
    __syncthreads();
    if (warp == 0) {
        float v = (lane < 8) ? red[lane] : 0.f;
#pragma unroll
        for (int o = 4; o; o >>= 1) v += __shfl_xor_sync(0xffffffffu, v, o);
        if (lane == 0) red[0] = v;
    }
    __syncthreads();
    float rs = rsqrtf(red[0] * (1.f / DM) + EPSF);

    float part = row * rs * nfw[n] * fcw[n];
#pragma unroll
    for (int o = 16; o; o >>= 1) part += __shfl_xor_sync(0xffffffffu, part, o);
    __syncthreads();
    if (lane == 0) red[warp] = part;
    __syncthreads();
    if (n == 0) {
        float s = 0.f;
#pragma unroll
        for (int w = 0; w < 8; w++) s += red[w];
        out[b] = s + fcb[0];
    }
}

// ---------------------------------------------------------------------------
extern "C" void kernel_launch(void* const* d_in, const int* in_sizes, int n_in,
                              void* d_out, int out_size)
{
    (void)in_sizes; (void)n_in; (void)out_size;
    const float* x    = (const float*)d_in[0];
    const float* nw   = (const float*)d_in[1];
    const float* ipw  = (const float*)d_in[2];
    const float* cw   = (const float*)d_in[3];
    const float* cb   = (const float*)d_in[4];
    const float* xpw  = (const float*)d_in[5];
    const float* dtw  = (const float*)d_in[6];
    const float* dtb  = (const float*)d_in[7];
    const float* alog = (const float*)d_in[8];
    const float* dsk  = (const float*)d_in[9];
    const float* opw  = (const float*)d_in[10];
    const float* nfw  = (const float*)d_in[11];
    const float* fcw  = (const float*)d_in[12];
    const float* fcb  = (const float*)d_in[13];

    float *X, *XZ, *DBC, *DELTA, *HC, *PC, *HIN, *PX, *PO, *YGF;
    __nv_bfloat16 *XNh, *XNl, *XIh, *XIl, *YGh, *YGl;
    __nv_bfloat16 *Wih, *Wil, *Wxh, *Wxl, *Woh, *Wol;
    cudaGetSymbolAddress((void**)&X,     g_X);
    cudaGetSymbolAddress((void**)&XZ,    g_XZ);
    cudaGetSymbolAddress((void**)&DBC,   g_DBC);
    cudaGetSymbolAddress((void**)&DELTA, g_DELTA);
    cudaGetSymbolAddress((void**)&HC,    g_HC);
    cudaGetSymbolAddress((void**)&PC,    g_PC);
    cudaGetSymbolAddress((void**)&HIN,   g_HIN);
    cudaGetSymbolAddress((void**)&PX,    g_PX);
    cudaGetSymbolAddress((void**)&PO,    g_PO);
    cudaGetSymbolAddress((void**)&YGF,   g_YGF);
    cudaGetSymbolAddress((void**)&XNh,   g_XNh);
    cudaGetSymbolAddress((void**)&XNl,   g_XNl);
    cudaGetSymbolAddress((void**)&XIh,   g_XIh);
    cudaGetSymbolAddress((void**)&XIl,   g_XIl);
    cudaGetSymbolAddress((void**)&YGh,   g_YGh);
    cudaGetSymbolAddress((void**)&YGl,   g_YGl);
    cudaGetSymbolAddress((void**)&Wih,   g_Wih);
    cudaGetSymbolAddress((void**)&Wil,   g_Wil);
    cudaGetSymbolAddress((void**)&Wxh,   g_Wxh);
    cudaGetSymbolAddress((void**)&Wxl,   g_Wxl);
    cudaGetSymbolAddress((void**)&Woh,   g_Woh);
    cudaGetSymbolAddress((void**)&Wol,   g_Wol);

    // slot 4 (ncu capture) = conv_silu_k (l=0): regression watch.
    rmsnorm_k<<<NT / 8, 256>>>(x, nw, XNh, XNl);                                   // 1
    repack_k<<<dim3(DM / 64, 1024 / 64, 2), 256>>>(ipw, Wih, Wil, DM, 2 * DI,      // 2
        (size_t)DM * 2 * DI, (size_t)1024 * DM);

    for (int l = 0; l < 2; l++) {
        if (l > 0)
            rmsnorm_k<<<NT / 8, 256>>>(X, nw + (size_t)l * DM, XNh, XNl);

        mma_gemm_k<128, 128><<<dim3(2 * DI / 128, NT / 128, 1), 256>>>(            // 3 (l=0)
            XNh, XNl, Wih + (size_t)l * 1024 * DM, Wil + (size_t)l * 1024 * DM,
            XZ, DM, DM, 2 * DI);

        conv_silu_k<<<dim3(DI / 128, L_SZ / CTT, B_SZ), 128>>>(                    // 4 (l=0)
            XZ, cw + (size_t)l * DI * DCNV, cb + (size_t)l * DI, XIh, XIl);

        if (l == 0)
            repack_k<<<dim3(DI / 64, 1, 2), 256>>>(xpw, Wxh, Wxl, DI, 48,
                (size_t)DI * 48, (size_t)64 * DI);

        mma_gemm_k<64, 64><<<dim3(1, NT / 64, 4), 256>>>(
            XIh, XIl, Wxh + (size_t)l * 64 * DI, Wxl + (size_t)l * 64 * DI,
            PX, DI, DI / 4, 64);

        delta_fused_k<<<NT / 64, 256>>>(PX, dtw + (size_t)l * DR * DI,
                                        dtb + (size_t)l * DI, DBC, DELTA);

        scan1_k<<<dim3(DI / 128, NCHUNK, B_SZ), 128>>>(
            DELTA, XIh, XIl, DBC, alog + (size_t)l * DI * DS, HC, PC);

        combine_k<<<dim3((DI * DS) / 256, B_SZ), 256>>>(HC, PC, HIN);

        if (l == 0) {
            scan2_k<false><<<dim3(DI / 128, NCHUNK, B_SZ), 128>>>(
                DELTA, XIh, XIl, DBC, alog + (size_t)l * DI * DS,
                dsk + (size_t)l * DI, HIN, XZ, YGh, YGl, YGF);

            repack_k<<<dim3(DI / 64, DM / 64, 1), 256>>>(opw, Woh, Wol, DI, DM,
                (size_t)DI * DM, (size_t)DM * DI);

            mma_gemm_k<128, 128><<<dim3(DM / 128, NT / 128, 2), 256>>>(
                YGh, YGl, Woh, Wol, PO, DI, DI / 2, DM);
            reduce2_resid_k<<<(NT * DM) / (4 * 256), 256>>>(PO, x, X, (NT * DM) / 4);
        } else {
            scan2_k<true><<<dim3(DI / 128, 1, B_SZ), 128>>>(
                DELTA, XIh, XIl, DBC, alog + (size_t)l * DI * DS,
                dsk + (size_t)l * DI, HIN, XZ, YGh, YGl, YGF);

            final2_k<<<B_SZ, 256>>>(X, YGF, opw + (size_t)1 * DI * DM,
                                    nfw, fcw, fcb, (float*)d_out);
        }
    }
}

// round 15
// speedup vs baseline: 1.0572x; 1.0572x over previous
#include <cuda_runtime.h>
#include <cuda_bf16.h>
#include <cstdint>
#include <cstddef>

// ---------------------------------------------------------------------------
// MambaSequenceClassifier: B=8, L=1024, D_MODEL=256, D_INNER=512, D_STATE=16,
// D_CONV=4, DT_RANK=16, N_LAYERS=2.
// Round 15: scan pipelining reverted (R14 regression).  rmsnorm(l=1) fused
// into out_proj reduce (X array dead except 8 last-token rows).  PC compressed
// to a scalar per (b,c,d) on the fast path.  Conv CTT=32.
// ---------------------------------------------------------------------------

#define B_SZ    8
#define L_SZ    1024
#define DM      256
#define DI      512
#define DS      16
#define DCNV    4
#define DR      16
#define NT      (B_SZ * L_SZ)        // 8192 tokens
#define NCHUNK  32
#define CLEN    (L_SZ / NCHUNK)      // 32
#define EPSF    1e-5f
#define PITCH   80
#define CTT     32                   // conv timesteps per thread

__device__ __forceinline__ uint32_t smem_to_u32(const void* p) {
    uint32_t a;
    asm("{ .reg .u64 t; cvta.to.shared.u64 t, %1; cvt.u32.u64 %0, t; }"
        : "=r"(a) : "l"(p));
    return a;
}
__device__ __forceinline__ void ldsm_x4(uint32_t (&r)[4], uint32_t addr) {
    asm volatile("ldmatrix.sync.aligned.m8n8.x4.shared.b16 {%0,%1,%2,%3}, [%4];"
        : "=r"(r[0]), "=r"(r[1]), "=r"(r[2]), "=r"(r[3]) : "r"(addr));
}
__device__ __forceinline__ void mma_bf16(float (&d)[4], const uint32_t (&a)[4],
                                         uint32_t b0, uint32_t b1) {
    asm volatile("mma.sync.aligned.m16n8k16.row.col.f32.bf16.bf16.f32 "
        "{%0,%1,%2,%3},{%4,%5,%6,%7},{%8,%9},{%0,%1,%2,%3};"
        : "+f"(d[0]), "+f"(d[1]), "+f"(d[2]), "+f"(d[3])
        : "r"(a[0]), "r"(a[1]), "r"(a[2]), "r"(a[3]), "r"(b0), "r"(b1));
}
__device__ __forceinline__ void cp_async16(uint32_t saddr, const void* gptr) {
    asm volatile("cp.async.cg.shared.global [%0], [%1], 16;"
        :: "r"(saddr), "l"(gptr));
}
#define CP_COMMIT() asm volatile("cp.async.commit_group;" ::: "memory")
template<int N>
__device__ __forceinline__ void cp_wait() {
    asm volatile("cp.async.wait_group %0;" :: "n"(N) : "memory");
}
__device__ __forceinline__ void split2(float x, __nv_bfloat16& hi, __nv_bfloat16& lo)
{
    hi = __float2bfloat16(x);
    lo = __float2bfloat16(x - __bfloat162float(hi));
}

// ---------------- device scratch (no allocation allowed) -------------------
__device__ float g_XZ   [NT * 2 * DI];
__device__ float g_DBC  [NT * 64];
__device__ float g_DELTA[NT * DI];
__device__ float g_HC   [B_SZ * NCHUNK * DI * DS];
__device__ float g_PC   [B_SZ * NCHUNK * DI * DS];   // slow-path only
__device__ float g_PCS  [B_SZ * NCHUNK * DI];        // fast-path scalar es
__device__ float g_HIN  [B_SZ * NCHUNK * DI * DS];
__device__ float g_PX   [4 * NT * 64];
__device__ float g_PO   [2 * NT * DM];
__device__ float g_YGF  [B_SZ * DI];
__device__ float g_XLAST[B_SZ * DM];                 // layer-1 residual, last token

__device__ __nv_bfloat16 g_XNh[NT * DM],  g_XNl[NT * DM];
__device__ __nv_bfloat16 g_XIh[NT * DI],  g_XIl[NT * DI];
__device__ __nv_bfloat16 g_YGh[NT * DI],  g_YGl[NT * DI];
__device__ __nv_bfloat16 g_Wih[2 * 1024 * DM], g_Wil[2 * 1024 * DM];
__device__ __nv_bfloat16 g_Wxh[2 * 64 * DI],   g_Wxl[2 * 64 * DI];
__device__ __nv_bfloat16 g_Woh[DM * DI],       g_Wol[DM * DI];

// ---------------------------------------------------------------------------
__global__ void repack_k(const float* __restrict__ W, __nv_bfloat16* __restrict__ Bh,
                         __nv_bfloat16* __restrict__ Bl, int K, int Norig,
                         size_t wstride, size_t bstride)
{
    __shared__ float t[64][65];
    int l = blockIdx.z;
    W  += (size_t)l * wstride;
    Bh += (size_t)l * bstride;
    Bl += (size_t)l * bstride;
    int k0 = blockIdx.x * 64, n0 = blockIdx.y * 64;
    int ty = threadIdx.x >> 6, tx = threadIdx.x & 63;

#pragma unroll
    for (int p = 0; p < 16; p++) {
        int k = k0 + p * 4 + ty;
        int n = n0 + tx;
        float v = (n < Norig) ? W[(size_t)k * Norig + n] : 0.f;
        t[tx][p * 4 + ty] = v;
    }
    __syncthreads();
#pragma unroll
    for (int p = 0; p < 16; p++) {
        int n = n0 + p * 4 + ty;
        int k = k0 + tx;
        float v = t[p * 4 + ty][tx];
        __nv_bfloat16 hi, lo;
        split2(v, hi, lo);
        Bh[(size_t)n * K + k] = hi;
        Bl[(size_t)n * K + k] = lo;
    }
}

// ---------------------------------------------------------------------------
// rmsnorm (layer 0: reads input x) -> bf16 hi/lo
// ---------------------------------------------------------------------------
__global__ void rmsnorm_k(const float* __restrict__ X, const float* __restrict__ w,
                          __nv_bfloat16* __restrict__ XNh, __nv_bfloat16* __restrict__ XNl)
{
    int warp = threadIdx.x >> 5, lane = threadIdx.x & 31;
    size_t row = (size_t)blockIdx.x * 8 + warp;
    const float* xr = X + row * DM;
    float v[8];
    float ss = 0.f;
#pragma unroll
    for (int i = 0; i < 8; i++) { v[i] = xr[lane + 32 * i]; ss += v[i] * v[i]; }
#pragma unroll
    for (int o = 16; o; o >>= 1) ss += __shfl_xor_sync(0xffffffffu, ss, o);
    float rs = rsqrtf(ss * (1.f / DM) + EPSF);
#pragma unroll
    for (int i = 0; i < 8; i++) {
        int j = lane + 32 * i;
        float y = v[i] * rs * w[j];
        __nv_bfloat16 hi, lo;
        split2(y, hi, lo);
        XNh[row * DM + j] = hi; XNl[row * DM + j] = lo;
    }
}

// ---------------------------------------------------------------------------
template<int BM, int BN>
__global__ void __launch_bounds__(256)
mma_gemm_k(const __nv_bfloat16* __restrict__ Ah, const __nv_bfloat16* __restrict__ Al,
           const __nv_bfloat16* __restrict__ Bh, const __nv_bfloat16* __restrict__ Bl,
           float* __restrict__ C, int Ktot, int klen, int ldc)
{
    constexpr int WM   = (BM == 128) ? 2 : 4;
    constexpr int WN   = 8 / WM;
    constexpr int MT   = BM / WM;
    constexpr int NTT  = BN / WN;
    constexpr int MT16 = MT / 16;
    constexpr int NP   = NTT / 16;
    constexpr int ABY  = BM * PITCH;
    constexpr int BBY  = BN * PITCH;
    constexpr int QA   = (BM * 4) / 256;
    constexpr int QB   = (BN * 4) / 256;

    __shared__ __align__(16) char sm[2][ABY + BBY];

    const int tid = threadIdx.x, wid = tid >> 5, lane = tid & 31;
    const int wm = wid % WM, wn = wid / WM;
    const int bn = blockIdx.x, bm = blockIdx.y;
    const int k0 = blockIdx.z * klen;
    const int zrow = blockIdx.z * gridDim.y * BM;

    uint32_t sA[2], sB[2];
#pragma unroll
    for (int s = 0; s < 2; s++) {
        sA[s] = smem_to_u32(sm[s]);
        sB[s] = sA[s] + ABY;
    }

    float acc[MT16][4][4];
#pragma unroll
    for (int i = 0; i < MT16; i++)
#pragma unroll
        for (int j = 0; j < 4; j++)
#pragma unroll
            for (int q = 0; q < 4; q++) acc[i][j][q] = 0.f;

    const int a_row = lane & 15;
    const int a_seg = lane >> 4;
    const int b_row = ((lane >> 4) << 3) | (lane & 7);
    const int b_seg = (lane >> 3) & 1;

    const int KC  = klen / 32;
    const int nkc = 3 * KC;

    auto issue = [&](int stage, int kc) {
        const int pl   = kc / KC;
        const int kcol = k0 + (kc - pl * KC) * 32;
        const __nv_bfloat16* Ap = (pl == 2) ? Al : Ah;
        const __nv_bfloat16* Bp = (pl == 1) ? Bl : Bh;
#pragma unroll
        for (int q = 0; q < QA; q++) {
            int f = tid + q * 256, r = f >> 2, s = f & 3;
            cp_async16(sA[stage] + r * PITCH + s * 16,
                       Ap + (size_t)(bm * BM + r) * Ktot + kcol + s * 8);
        }
#pragma unroll
        for (int q = 0; q < QB; q++) {
            int f = tid + q * 256, r = f >> 2, s = f & 3;
            cp_async16(sB[stage] + r * PITCH + s * 16,
                       Bp + (size_t)(bn * BN + r) * Ktot + kcol + s * 8);
        }
    };

    issue(0, 0);
    CP_COMMIT();

    for (int kc = 0; kc < nkc; kc++) {
        const int buf = kc & 1;
        if (kc + 1 < nkc) {
            issue(buf ^ 1, kc + 1);
            CP_COMMIT();
            cp_wait<1>();
        } else {
            cp_wait<0>();
        }
        __syncthreads();

#pragma unroll
        for (int k16 = 0; k16 < 2; k16++) {
            uint32_t afr[MT16][4], bfr[NP][4];
#pragma unroll
            for (int mt = 0; mt < MT16; mt++) {
                int row = wm * MT + mt * 16 + a_row;
                ldsm_x4(afr[mt], sA[buf] + row * PITCH + (k16 * 2 + a_seg) * 16);
            }
#pragma unroll
            for (int np = 0; np < NP; np++) {
                int row = wn * NTT + np * 16 + b_row;
                ldsm_x4(bfr[np], sB[buf] + row * PITCH + (k16 * 2 + b_seg) * 16);
            }
#pragma unroll
            for (int mt = 0; mt < MT16; mt++)
#pragma unroll
                for (int np = 0; np < NP; np++) {
                    mma_bf16(acc[mt][2 * np + 0], afr[mt], bfr[np][0], bfr[np][1]);
                    mma_bf16(acc[mt][2 * np + 1], afr[mt], bfr[np][2], bfr[np][3]);
                }
        }
        __syncthreads();
    }

    const int r0 = zrow + bm * BM + wm * MT + (lane >> 2);
    const int c0 = bn * BN + wn * NTT + (lane & 3) * 2;
#pragma unroll
    for (int mt = 0; mt < MT16; mt++) {
#pragma unroll
        for (int nt = 0; nt < 4; nt++) {
            int row = r0 + mt * 16;
            int col = c0 + nt * 8;
            *(float2*)(C + (size_t)row * ldc + col) =
                make_float2(acc[mt][nt][0], acc[mt][nt][1]);
            *(float2*)(C + (size_t)(row + 8) * ldc + col) =
                make_float2(acc[mt][nt][2], acc[mt][nt][3]);
        }
    }
}

// ---------------------------------------------------------------------------
// out_proj reduce + residual + layer-1 rmsnorm, fused.
// One warp per token row: row = x + P0 + P1; emits rmsnorm(row)*w -> bf16 hi/lo.
// Last token of each batch also stores the raw residual row to Xlast.
// ---------------------------------------------------------------------------
__global__ void __launch_bounds__(256)
reduce2rms_k(const float* __restrict__ P, const float* __restrict__ xin,
             const float* __restrict__ w,
             __nv_bfloat16* __restrict__ XNh, __nv_bfloat16* __restrict__ XNl,
             float* __restrict__ Xlast)
{
    int warp = threadIdx.x >> 5, lane = threadIdx.x & 31;
    size_t m = (size_t)blockIdx.x * 8 + warp;
    const float* p0 = P + m * DM;
    const float* p1 = P + (size_t)NT * DM + m * DM;
    const float* xr = xin + m * DM;

    float v[8];
    float ss = 0.f;
#pragma unroll
    for (int i = 0; i < 8; i++) {
        int j = lane + 32 * i;
        v[i] = xr[j] + p0[j] + p1[j];
        ss += v[i] * v[i];
    }
#pragma unroll
    for (int o = 16; o; o >>= 1) ss += __shfl_xor_sync(0xffffffffu, ss, o);
    float rs = rsqrtf(ss * (1.f / DM) + EPSF);

    bool last = ((m & (L_SZ - 1)) == (L_SZ - 1));
    int  bidx = (int)(m >> 10);   // m / L_SZ
#pragma unroll
    for (int i = 0; i < 8; i++) {
        int j = lane + 32 * i;
        float y = v[i] * rs * w[j];
        __nv_bfloat16 hi, lo;
        split2(y, hi, lo);
        XNh[m * DM + j] = hi; XNl[m * DM + j] = lo;
        if (last) Xlast[(size_t)bidx * DM + j] = v[i];
    }
}

// ---------------------------------------------------------------------------
// fused x_proj reduce (4 slabs) + delta
// ---------------------------------------------------------------------------
__global__ void __launch_bounds__(256)
delta_fused_k(const float* __restrict__ PX, const float* __restrict__ dtw,
              const float* __restrict__ dtb, float* __restrict__ DBC,
              float* __restrict__ DELTA)
{
    __shared__ float sr[64][DR];
    const int tid = threadIdx.x;
    const size_t m0 = (size_t)blockIdx.x * 64;
    const int n4tot = NT * 16;

#pragma unroll
    for (int q = 0; q < 4; q++) {
        int f = tid + q * 256;
        int t = f >> 4, c4 = (f & 15);
        size_t o = (m0 + t) * 16 + c4;
        const float4* p = (const float4*)PX;
        float4 a = p[o], b = p[o + n4tot], c = p[o + 2 * n4tot], d = p[o + 3 * n4tot];
        float4 r;
        r.x = (a.x + b.x) + (c.x + d.x);
        r.y = (a.y + b.y) + (c.y + d.y);
        r.z = (a.z + b.z) + (c.z + d.z);
        r.w = (a.w + b.w) + (c.w + d.w);
        ((float4*)DBC)[o] = r;
        if (c4 < 4) *(float4*)(&sr[t][c4 * 4]) = r;
    }
    __syncthreads();

    int d0 = tid, d1 = tid + 256;
    float wt0[DR], wt1[DR];
#pragma unroll
    for (int r = 0; r < DR; r++) {
        wt0[r] = dtw[r * DI + d0];
        wt1[r] = dtw[r * DI + d1];
    }
    float b0 = dtb[d0], b1 = dtb[d1];

#pragma unroll 4
    for (int t = 0; t < 64; t++) {
        float a0 = b0, a1 = b1;
#pragma unroll
        for (int r = 0; r < DR; r++) {
            float s = sr[t][r];
            a0 += s * wt0[r];
            a1 += s * wt1[r];
        }
        float sp0 = fmaxf(a0, 0.f) + __logf(1.f + __expf(-fabsf(a0)));
        float sp1 = fmaxf(a1, 0.f) + __logf(1.f + __expf(-fabsf(a1)));
        DELTA[(m0 + t) * DI + d0] = sp0;
        DELTA[(m0 + t) * DI + d1] = sp1;
    }
}

// ---------------------------------------------------------------------------
// causal depthwise conv (width 4) + bias + silu, CTT=32 timesteps/thread
// ---------------------------------------------------------------------------
__global__ void __launch_bounds__(128)
conv_silu_k(const float* __restrict__ XZ, const float* __restrict__ cw,
            const float* __restrict__ cb,
            __nv_bfloat16* __restrict__ XIh, __nv_bfloat16* __restrict__ XIl)
{
    int d  = blockIdx.x * 128 + threadIdx.x;
    int b  = blockIdx.z;
    int t0 = blockIdx.y * CTT;

    float w0 = cw[d * 4 + 0], w1 = cw[d * 4 + 1];
    float w2 = cw[d * 4 + 2], w3 = cw[d * 4 + 3];
    float bias = cb[d];

    const float* base = XZ + (size_t)b * L_SZ * (2 * DI) + d;

    float v[CTT + 3];
    v[0] = (t0 - 3 >= 0) ? base[(size_t)(t0 - 3) * (2 * DI)] : 0.f;
    v[1] = (t0 - 2 >= 0) ? base[(size_t)(t0 - 2) * (2 * DI)] : 0.f;
    v[2] = (t0 - 1 >= 0) ? base[(size_t)(t0 - 1) * (2 * DI)] : 0.f;
#pragma unroll
    for (int i = 0; i < CTT; i++)
        v[i + 3] = base[(size_t)(t0 + i) * (2 * DI)];

    size_t o = ((size_t)b * L_SZ + t0) * DI + d;
#pragma unroll
    for (int i = 0; i < CTT; i++) {
        float y = w0 * v[i] + w1 * v[i + 1] + w2 * v[i + 2] + w3 * v[i + 3] + bias;
        y = y / (1.f + __expf(-y));
        __nv_bfloat16 hi, lo;
        split2(y, hi, lo);
        XIh[o + (size_t)i * DI] = hi;
        XIl[o + (size_t)i * DI] = lo;
    }
}

// ---------------------------------------------------------------------------
// scan pass 1 (R13 body).  Fast path stores only es -> PCS; slow path stores
// full PC and sets PCS = NaN.
// ---------------------------------------------------------------------------
__global__ void __launch_bounds__(128)
scan1_k(const float* __restrict__ DELTA,
        const __nv_bfloat16* __restrict__ XIh, const __nv_bfloat16* __restrict__ XIl,
        const float* __restrict__ DBC, const float* __restrict__ alog,
        float* __restrict__ HC, float* __restrict__ PC, float* __restrict__ PCS)
{
    __shared__ float sB[CLEN][DS];
    int d = blockIdx.x * 128 + threadIdx.x;
    int c = blockIdx.y, b = blockIdx.z;
    size_t m0 = (size_t)b * L_SZ + (size_t)c * CLEN;

    for (int j = threadIdx.x; j < CLEN * DS; j += 128) {
        int i = j >> 4, n = j & 15;
        sB[i][n] = DBC[(m0 + i) * 64 + 16 + n];
    }

    float an[DS];
#pragma unroll
    for (int n = 0; n < DS; n++) an[n] = -__expf(alog[(size_t)d * DS + n]);
    float a0 = an[0];
    bool fast = true;
#pragma unroll
    for (int n = 1; n < DS; n++)
        if (fabsf(an[n] - a0 * (n + 1)) > 1e-4f * fabsf(an[n])) fast = false;
    __syncthreads();

    float h[DS];
#pragma unroll
    for (int n = 0; n < DS; n++) h[n] = 0.f;

    const float* dp = DELTA + m0 * DI + d;
    const __nv_bfloat16* uph = XIh + m0 * DI + d;
    const __nv_bfloat16* upl = XIl + m0 * DI + d;

    size_t o  = (((size_t)b * NCHUNK + c) * DI + d) * DS;
    size_t os = ((size_t)b * NCHUNK + c) * DI + d;

    if (fast) {
        float sdl = 0.f;
        for (int t = 0; t < CLEN; t++) {
            float dl = dp[(size_t)t * DI];
            float u  = __bfloat162float(uph[(size_t)t * DI])
                     + __bfloat162float(upl[(size_t)t * DI]);
            float du = dl * u;
            sdl += dl;
            float e1 = __expf(dl * a0);
            float pw[DS];
            pw[0] = e1;
            pw[1] = e1 * e1;
            pw[2] = pw[1] * e1;
            pw[3] = pw[1] * pw[1];
#pragma unroll
            for (int n = 4; n < DS; n++) pw[n] = pw[n - 4] * pw[3];
#pragma unroll
            for (int n = 0; n < DS; n++)
                h[n] = pw[n] * h[n] + du * sB[t][n];
        }
        PCS[os] = __expf(a0 * sdl);
    } else {
        float p[DS];
#pragma unroll
        for (int n = 0; n < DS; n++) p[n] = 1.f;
        for (int t = 0; t < CLEN; t++) {
            float dl = dp[(size_t)t * DI];
            float u  = __bfloat162float(uph[(size_t)t * DI])
                     + __bfloat162float(upl[(size_t)t * DI]);
            float du = dl * u;
#pragma unroll
            for (int n = 0; n < DS; n++) {
                float dA = __expf(dl * an[n]);
                h[n] = dA * h[n] + du * sB[t][n];
                p[n] *= dA;
            }
        }
#pragma unroll
        for (int n = 0; n < DS; n++) PC[o + n] = p[n];
        PCS[os] = __int_as_float(0x7fffffff);   // NaN sentinel
    }

#pragma unroll
    for (int n = 0; n < DS; n++) HC[o + n] = h[n];
}

// ---------------------------------------------------------------------------
// combine: p from PCS scalar (es^(n+1) via binary exponentiation) or PC array
// ---------------------------------------------------------------------------
__global__ void __launch_bounds__(256)
combine_k(const float* __restrict__ HC, const float* __restrict__ PC,
          const float* __restrict__ PCS, float* __restrict__ HIN)
{
    int b = blockIdx.y;
    int idx = blockIdx.x * 256 + threadIdx.x;   // d*16 + n
    int d = idx >> 4, n = idx & 15;
    int m = n + 1;
    float hin = 0.f;
#pragma unroll 4
    for (int c = 0; c < NCHUNK; c++) {
        size_t base = ((size_t)b * NCHUNK + c) * DI;
        float es = PCS[base + d];
        float p;
        if (isnan(es)) {
            p = PC[(base + d) * DS + n];
        } else {
            float e2 = es * es, e4 = e2 * e2, e8 = e4 * e4;
            p = 1.f;
            if (m & 1)  p *= es;
            if (m & 2)  p *= e2;
            if (m & 4)  p *= e4;
            if (m & 8)  p *= e8;
            if (m & 16) p *= e8 * e8;
        }
        size_t o = (base + d) * DS + n;
        float hc = HC[o];
        HIN[o] = hin;
        hin = p * hin + hc;
    }
}

// ---------------------------------------------------------------------------
// scan pass 2 + gating (R13 body)
// ---------------------------------------------------------------------------
template<bool LAST_ONLY>
__global__ void __launch_bounds__(128)
scan2_k(const float* __restrict__ DELTA,
        const __nv_bfloat16* __restrict__ XIh, const __nv_bfloat16* __restrict__ XIl,
        const float* __restrict__ DBC, const float* __restrict__ alog,
        const float* __restrict__ dsk, const float* __restrict__ HIN,
        const float* __restrict__ XZ,
        __nv_bfloat16* __restrict__ YGh, __nv_bfloat16* __restrict__ YGl,
        float* __restrict__ YGF)
{
    __shared__ float sB[CLEN][DS];
    __shared__ float sC[CLEN][DS];
    int d = blockIdx.x * 128 + threadIdx.x;
    int c = LAST_ONLY ? (NCHUNK - 1) : blockIdx.y;
    int b = blockIdx.z;
    size_t m0 = (size_t)b * L_SZ + (size_t)c * CLEN;

    for (int j = threadIdx.x; j < CLEN * DS; j += 128) {
        int i = j >> 4, n = j & 15;
        sB[i][n] = DBC[(m0 + i) * 64 + 16 + n];
        sC[i][n] = DBC[(m0 + i) * 64 + 32 + n];
    }

    float an[DS];
#pragma unroll
    for (int n = 0; n < DS; n++) an[n] = -__expf(alog[(size_t)d * DS + n]);
    float a0 = an[0];
    bool fast = true;
#pragma unroll
    for (int n = 1; n < DS; n++)
        if (fabsf(an[n] - a0 * (n + 1)) > 1e-4f * fabsf(an[n])) fast = false;
    __syncthreads();

    float h[DS];
    size_t o = (((size_t)b * NCHUNK + c) * DI + d) * DS;
#pragma unroll
    for (int n = 0; n < DS; n++) h[n] = HIN[o + n];

    float Dd = dsk[d];
    const float* dp = DELTA + m0 * DI + d;
    const __nv_bfloat16* uph = XIh + m0 * DI + d;
    const __nv_bfloat16* upl = XIl + m0 * DI + d;
    const float* zp = XZ + m0 * (2 * DI) + DI + d;

    for (int t = 0; t < CLEN; t++) {
        float dl = dp[(size_t)t * DI];
        float u  = __bfloat162float(uph[(size_t)t * DI])
                 + __bfloat162float(upl[(size_t)t * DI]);
        float du = dl * u;
        float y0 = 0.f, y1 = 0.f, y2 = 0.f, y3 = 0.f;
        bool emit = !LAST_ONLY || (t == CLEN - 1);
        if (fast) {
            float e1 = __expf(dl * a0);
            float pw[DS];
            pw[0] = e1;
            pw[1] = e1 * e1;
            pw[2] = pw[1] * e1;
            pw[3] = pw[1] * pw[1];
#pragma unroll
            for (int n = 4; n < DS; n++) pw[n] = pw[n - 4] * pw[3];
#pragma unroll
            for (int n = 0; n < DS; n += 4) {
                h[n + 0] = pw[n + 0] * h[n + 0] + du * sB[t][n + 0];
                h[n + 1] = pw[n + 1] * h[n + 1] + du * sB[t][n + 1];
                h[n + 2] = pw[n + 2] * h[n + 2] + du * sB[t][n + 2];
                h[n + 3] = pw[n + 3] * h[n + 3] + du * sB[t][n + 3];
                y0 += h[n + 0] * sC[t][n + 0];
                y1 += h[n + 1] * sC[t][n + 1];
                y2 += h[n + 2] * sC[t][n + 2];
                y3 += h[n + 3] * sC[t][n + 3];
            }
        } else {
#pragma unroll
            for (int n = 0; n < DS; n++) {
                float dA = __expf(dl * an[n]);
                h[n] = dA * h[n] + du * sB[t][n];
                y0 += h[n] * sC[t][n];
            }
        }
        if (emit) {
            float y = (y0 + y1) + (y2 + y3);
            float z = zp[(size_t)t * (2 * DI)];
            float g = z / (1.f + __expf(-z));
            float out = (y + u * Dd) * g;
            if (LAST_ONLY) {
                YGF[(size_t)b * DI + d] = out;
            } else {
                __nv_bfloat16 hi, lo;
                split2(out, hi, lo);
                YGh[m0 * DI + (size_t)t * DI + d] = hi;
                YGl[m0 * DI + (size_t)t * DI + d] = lo;
            }
        }
    }
}

// ---------------------------------------------------------------------------
// fused classifier head; residual row comes from Xlast (B x DM)
// ---------------------------------------------------------------------------
__global__ void __launch_bounds__(256)
final2_k(const float* __restrict__ Xlast, const float* __restrict__ YGF,
         const float* __restrict__ opw1,
         const float* __restrict__ nfw, const float* __restrict__ fcw,
         const float* __restrict__ fcb, float* __restrict__ out)
{
    __shared__ float yg[DI];
    __shared__ float red[8];
    int b = blockIdx.x, n = threadIdx.x;
    int warp = n >> 5, lane = n & 31;

    for (int k = n; k < DI; k += 256) yg[k] = YGF[(size_t)b * DI + k];
    __syncthreads();

    float acc = 0.f;
#pragma unroll 4
    for (int k = 0; k < DI; k++)
        acc += yg[k] * opw1[(size_t)k * DM + n];

    float row = Xlast[(size_t)b * DM + n] + acc;

    float ss = row * row;
#pragma unroll
    for (int o = 16; o; o >>= 1) ss += __shfl_xor_sync(0xffffffffu, ss, o);
    if (lane == 0) red[warp] = ss;
    __syncthreads();
    if (warp == 0) {
        float v = (lane < 8) ? red[lane] : 0.f;
#pragma unroll
        for (int o = 4; o; o >>= 1) v += __shfl_xor_sync(0xffffffffu, v, o);
        if (lane == 0) red[0] = v;
    }
    __syncthreads();
    float rs = rsqrtf(red[0] * (1.f / DM) + EPSF);

    float part = row * rs * nfw[n] * fcw[n];
#pragma unroll
    for (int o = 16; o; o >>= 1) part += __shfl_xor_sync(0xffffffffu, part, o);
    __syncthreads();
    if (lane == 0) red[warp] = part;
    __syncthreads();
    if (n == 0) {
        float s = 0.f;
#pragma unroll
        for (int w = 0; w < 8; w++) s += red[w];
        out[b] = s + fcb[0];
    }
}

// ---------------------------------------------------------------------------
extern "C" void kernel_launch(void* const* d_in, const int* in_sizes, int n_in,
                              void* d_out, int out_size)
{
    (void)in_sizes; (void)n_in; (void)out_size;
    const float* x    = (const float*)d_in[0];
    const float* nw   = (const float*)d_in[1];
    const float* ipw  = (const float*)d_in[2];
    const float* cw   = (const float*)d_in[3];
    const float* cb   = (const float*)d_in[4];
    const float* xpw  = (const float*)d_in[5];
    const float* dtw  = (const float*)d_in[6];
    const float* dtb  = (const float*)d_in[7];
    const float* alog = (const float*)d_in[8];
    const float* dsk  = (const float*)d_in[9];
    const float* opw  = (const float*)d_in[10];
    const float* nfw  = (const float*)d_in[11];
    const float* fcw  = (const float*)d_in[12];
    const float* fcb  = (const float*)d_in[13];

    float *XZ, *DBC, *DELTA, *HC, *PC, *PCS, *HIN, *PX, *PO, *YGF, *XLAST;
    __nv_bfloat16 *XNh, *XNl, *XIh, *XIl, *YGh, *YGl;
    __nv_bfloat16 *Wih, *Wil, *Wxh, *Wxl, *Woh, *Wol;
    cudaGetSymbolAddress((void**)&XZ,    g_XZ);
    cudaGetSymbolAddress((void**)&DBC,   g_DBC);
    cudaGetSymbolAddress((void**)&DELTA, g_DELTA);
    cudaGetSymbolAddress((void**)&HC,    g_HC);
    cudaGetSymbolAddress((void**)&PC,    g_PC);
    cudaGetSymbolAddress((void**)&PCS,   g_PCS);
    cudaGetSymbolAddress((void**)&HIN,   g_HIN);
    cudaGetSymbolAddress((void**)&PX,    g_PX);
    cudaGetSymbolAddress((void**)&PO,    g_PO);
    cudaGetSymbolAddress((void**)&YGF,   g_YGF);
    cudaGetSymbolAddress((void**)&XLAST, g_XLAST);
    cudaGetSymbolAddress((void**)&XNh,   g_XNh);
    cudaGetSymbolAddress((void**)&XNl,   g_XNl);
    cudaGetSymbolAddress((void**)&XIh,   g_XIh);
    cudaGetSymbolAddress((void**)&XIl,   g_XIl);
    cudaGetSymbolAddress((void**)&YGh,   g_YGh);
    cudaGetSymbolAddress((void**)&YGl,   g_YGl);
    cudaGetSymbolAddress((void**)&Wih,   g_Wih);
    cudaGetSymbolAddress((void**)&Wil,   g_Wil);
    cudaGetSymbolAddress((void**)&Wxh,   g_Wxh);
    cudaGetSymbolAddress((void**)&Wxl,   g_Wxl);
    cudaGetSymbolAddress((void**)&Woh,   g_Woh);
    cudaGetSymbolAddress((void**)&Wol,   g_Wol);

    // slot 4 (ncu capture) = conv_silu_k (l=0): verifies CTT=32.
    rmsnorm_k<<<NT / 8, 256>>>(x, nw, XNh, XNl);                                   // 1
    repack_k<<<dim3(DM / 64, 1024 / 64, 2), 256>>>(ipw, Wih, Wil, DM, 2 * DI,      // 2
        (size_t)DM * 2 * DI, (size_t)1024 * DM);

    for (int l = 0; l < 2; l++) {
        // (layer-1 rmsnorm is fused into reduce2rms_k below)

        mma_gemm_k<128, 128><<<dim3(2 * DI / 128, NT / 128, 1), 256>>>(            // 3 (l=0)
            XNh, XNl, Wih + (size_t)l * 1024 * DM, Wil + (size_t)l * 1024 * DM,
            XZ, DM, DM, 2 * DI);

        conv_silu_k<<<dim3(DI / 128, L_SZ / CTT, B_SZ), 128>>>(                    // 4 (l=0)
            XZ, cw + (size_t)l * DI * DCNV, cb + (size_t)l * DI, XIh, XIl);

        if (l == 0)
            repack_k<<<dim3(DI / 64, 1, 2), 256>>>(xpw, Wxh, Wxl, DI, 48,
                (size_t)DI * 48, (size_t)64 * DI);

        mma_gemm_k<64, 64><<<dim3(1, NT / 64, 4), 256>>>(
            XIh, XIl, Wxh + (size_t)l * 64 * DI, Wxl + (size_t)l * 64 * DI,
            PX, DI, DI / 4, 64);

        delta_fused_k<<<NT / 64, 256>>>(PX, dtw + (size_t)l * DR * DI,
                                        dtb + (size_t)l * DI, DBC, DELTA);

        scan1_k<<<dim3(DI / 128, NCHUNK, B_SZ), 128>>>(
            DELTA, XIh, XIl, DBC, alog + (size_t)l * DI * DS, HC, PC, PCS);

        combine_k<<<dim3((DI * DS) / 256, B_SZ), 256>>>(HC, PC, PCS, HIN);

        if (l == 0) {
            scan2_k<false><<<dim3(DI / 128, NCHUNK, B_SZ), 128>>>(
                DELTA, XIh, XIl, DBC, alog + (size_t)l * DI * DS,
                dsk + (size_t)l * DI, HIN, XZ, YGh, YGl, YGF);

            repack_k<<<dim3(DI / 64, DM / 64, 1), 256>>>(opw, Woh, Wol, DI, DM,
                (size_t)DI * DM, (size_t)DM * DI);

            mma_gemm_k<128, 128><<<dim3(DM / 128, NT / 128, 2), 256>>>(
                YGh, YGl, Woh, Wol, PO, DI, DI / 2, DM);

            // fused: X' = x + P0 + P1; rmsnorm(layer 1) -> XNh/XNl; Xlast rows
            reduce2rms_k<<<NT / 8, 256>>>(PO, x, nw + DM, XNh, XNl, XLAST);
        } else {
            scan2_k<true><<<dim3(DI / 128, 1, B_SZ), 128>>>(
                DELTA, XIh, XIl, DBC, alog + (size_t)l * DI * DS,
                dsk + (size_t)l * DI, HIN, XZ, YGh, YGl, YGF);

            final2_k<<<B_SZ, 256>>>(XLAST, YGF, opw + (size_t)1 * DI * DM,
                                    nfw, fcw, fcb, (float*)d_out);
        }
    }
}

// round 16
// speedup vs baseline: 1.0719x; 1.0139x over previous
#include <cuda_runtime.h>
#include <cuda_bf16.h>
#include <cstdint>
#include <cstddef>

// ---------------------------------------------------------------------------
// MambaSequenceClassifier: B=8, L=1024, D_MODEL=256, D_INNER=512, D_STATE=16,
// D_CONV=4, DT_RANK=16, N_LAYERS=2.
// Round 16: conv CTT reverted to 16 (measured optimum); __ldcs streaming
// eviction on single-use bulk reads (PX, PO, HIN); scan2 LAST_ONLY skips the
// y-dot except at the emitting step.  Everything else frozen at R15.
// ---------------------------------------------------------------------------

#define B_SZ    8
#define L_SZ    1024
#define DM      256
#define DI      512
#define DS      16
#define DCNV    4
#define DR      16
#define NT      (B_SZ * L_SZ)        // 8192 tokens
#define NCHUNK  32
#define CLEN    (L_SZ / NCHUNK)      // 32
#define EPSF    1e-5f
#define PITCH   80
#define CTT     16                   // conv timesteps per thread (R13 optimum)

__device__ __forceinline__ uint32_t smem_to_u32(const void* p) {
    uint32_t a;
    asm("{ .reg .u64 t; cvta.to.shared.u64 t, %1; cvt.u32.u64 %0, t; }"
        : "=r"(a) : "l"(p));
    return a;
}
__device__ __forceinline__ void ldsm_x4(uint32_t (&r)[4], uint32_t addr) {
    asm volatile("ldmatrix.sync.aligned.m8n8.x4.shared.b16 {%0,%1,%2,%3}, [%4];"
        : "=r"(r[0]), "=r"(r[1]), "=r"(r[2]), "=r"(r[3]) : "r"(addr));
}
__device__ __forceinline__ void mma_bf16(float (&d)[4], const uint32_t (&a)[4],
                                         uint32_t b0, uint32_t b1) {
    asm volatile("mma.sync.aligned.m16n8k16.row.col.f32.bf16.bf16.f32 "
        "{%0,%1,%2,%3},{%4,%5,%6,%7},{%8,%9},{%0,%1,%2,%3};"
        : "+f"(d[0]), "+f"(d[1]), "+f"(d[2]), "+f"(d[3])
        : "r"(a[0]), "r"(a[1]), "r"(a[2]), "r"(a[3]), "r"(b0), "r"(b1));
}
__device__ __forceinline__ void cp_async16(uint32_t saddr, const void* gptr) {
    asm volatile("cp.async.cg.shared.global [%0], [%1], 16;"
        :: "r"(saddr), "l"(gptr));
}
#define CP_COMMIT() asm volatile("cp.async.commit_group;" ::: "memory")
template<int N>
__device__ __forceinline__ void cp_wait() {
    asm volatile("cp.async.wait_group %0;" :: "n"(N) : "memory");
}
__device__ __forceinline__ void split2(float x, __nv_bfloat16& hi, __nv_bfloat16& lo)
{
    hi = __float2bfloat16(x);
    lo = __float2bfloat16(x - __bfloat162float(hi));
}
__device__ __forceinline__ float4 ldcs4(const float4* p) {
    return __ldcs(p);
}

// ---------------- device scratch (no allocation allowed) -------------------
__device__ float g_XZ   [NT * 2 * DI];
__device__ float g_DBC  [NT * 64];
__device__ float g_DELTA[NT * DI];
__device__ float g_HC   [B_SZ * NCHUNK * DI * DS];
__device__ float g_PC   [B_SZ * NCHUNK * DI * DS];   // slow-path only
__device__ float g_PCS  [B_SZ * NCHUNK * DI];        // fast-path scalar es
__device__ float g_HIN  [B_SZ * NCHUNK * DI * DS];
__device__ float g_PX   [4 * NT * 64];
__device__ float g_PO   [2 * NT * DM];
__device__ float g_YGF  [B_SZ * DI];
__device__ float g_XLAST[B_SZ * DM];

__device__ __nv_bfloat16 g_XNh[NT * DM],  g_XNl[NT * DM];
__device__ __nv_bfloat16 g_XIh[NT * DI],  g_XIl[NT * DI];
__device__ __nv_bfloat16 g_YGh[NT * DI],  g_YGl[NT * DI];
__device__ __nv_bfloat16 g_Wih[2 * 1024 * DM], g_Wil[2 * 1024 * DM];
__device__ __nv_bfloat16 g_Wxh[2 * 64 * DI],   g_Wxl[2 * 64 * DI];
__device__ __nv_bfloat16 g_Woh[DM * DI],       g_Wol[DM * DI];

// ---------------------------------------------------------------------------
__global__ void repack_k(const float* __restrict__ W, __nv_bfloat16* __restrict__ Bh,
                         __nv_bfloat16* __restrict__ Bl, int K, int Norig,
                         size_t wstride, size_t bstride)
{
    __shared__ float t[64][65];
    int l = blockIdx.z;
    W  += (size_t)l * wstride;
    Bh += (size_t)l * bstride;
    Bl += (size_t)l * bstride;
    int k0 = blockIdx.x * 64, n0 = blockIdx.y * 64;
    int ty = threadIdx.x >> 6, tx = threadIdx.x & 63;

#pragma unroll
    for (int p = 0; p < 16; p++) {
        int k = k0 + p * 4 + ty;
        int n = n0 + tx;
        float v = (n < Norig) ? W[(size_t)k * Norig + n] : 0.f;
        t[tx][p * 4 + ty] = v;
    }
    __syncthreads();
#pragma unroll
    for (int p = 0; p < 16; p++) {
        int n = n0 + p * 4 + ty;
        int k = k0 + tx;
        float v = t[p * 4 + ty][tx];
        __nv_bfloat16 hi, lo;
        split2(v, hi, lo);
        Bh[(size_t)n * K + k] = hi;
        Bl[(size_t)n * K + k] = lo;
    }
}

// ---------------------------------------------------------------------------
__global__ void rmsnorm_k(const float* __restrict__ X, const float* __restrict__ w,
                          __nv_bfloat16* __restrict__ XNh, __nv_bfloat16* __restrict__ XNl)
{
    int warp = threadIdx.x >> 5, lane = threadIdx.x & 31;
    size_t row = (size_t)blockIdx.x * 8 + warp;
    const float* xr = X + row * DM;
    float v[8];
    float ss = 0.f;
#pragma unroll
    for (int i = 0; i < 8; i++) { v[i] = xr[lane + 32 * i]; ss += v[i] * v[i]; }
#pragma unroll
    for (int o = 16; o; o >>= 1) ss += __shfl_xor_sync(0xffffffffu, ss, o);
    float rs = rsqrtf(ss * (1.f / DM) + EPSF);
#pragma unroll
    for (int i = 0; i < 8; i++) {
        int j = lane + 32 * i;
        float y = v[i] * rs * w[j];
        __nv_bfloat16 hi, lo;
        split2(y, hi, lo);
        XNh[row * DM + j] = hi; XNl[row * DM + j] = lo;
    }
}

// ---------------------------------------------------------------------------
template<int BM, int BN>
__global__ void __launch_bounds__(256)
mma_gemm_k(const __nv_bfloat16* __restrict__ Ah, const __nv_bfloat16* __restrict__ Al,
           const __nv_bfloat16* __restrict__ Bh, const __nv_bfloat16* __restrict__ Bl,
           float* __restrict__ C, int Ktot, int klen, int ldc)
{
    constexpr int WM   = (BM == 128) ? 2 : 4;
    constexpr int WN   = 8 / WM;
    constexpr int MT   = BM / WM;
    constexpr int NTT  = BN / WN;
    constexpr int MT16 = MT / 16;
    constexpr int NP   = NTT / 16;
    constexpr int ABY  = BM * PITCH;
    constexpr int BBY  = BN * PITCH;
    constexpr int QA   = (BM * 4) / 256;
    constexpr int QB   = (BN * 4) / 256;

    __shared__ __align__(16) char sm[2][ABY + BBY];

    const int tid = threadIdx.x, wid = tid >> 5, lane = tid & 31;
    const int wm = wid % WM, wn = wid / WM;
    const int bn = blockIdx.x, bm = blockIdx.y;
    const int k0 = blockIdx.z * klen;
    const int zrow = blockIdx.z * gridDim.y * BM;

    uint32_t sA[2], sB[2];
#pragma unroll
    for (int s = 0; s < 2; s++) {
        sA[s] = smem_to_u32(sm[s]);
        sB[s] = sA[s] + ABY;
    }

    float acc[MT16][4][4];
#pragma unroll
    for (int i = 0; i < MT16; i++)
#pragma unroll
        for (int j = 0; j < 4; j++)
#pragma unroll
            for (int q = 0; q < 4; q++) acc[i][j][q] = 0.f;

    const int a_row = lane & 15;
    const int a_seg = lane >> 4;
    const int b_row = ((lane >> 4) << 3) | (lane & 7);
    const int b_seg = (lane >> 3) & 1;

    const int KC  = klen / 32;
    const int nkc = 3 * KC;

    auto issue = [&](int stage, int kc) {
        const int pl   = kc / KC;
        const int kcol = k0 + (kc - pl * KC) * 32;
        const __nv_bfloat16* Ap = (pl == 2) ? Al : Ah;
        const __nv_bfloat16* Bp = (pl == 1) ? Bl : Bh;
#pragma unroll
        for (int q = 0; q < QA; q++) {
            int f = tid + q * 256, r = f >> 2, s = f & 3;
            cp_async16(sA[stage] + r * PITCH + s * 16,
                       Ap + (size_t)(bm * BM + r) * Ktot + kcol + s * 8);
        }
#pragma unroll
        for (int q = 0; q < QB; q++) {
            int f = tid + q * 256, r = f >> 2, s = f & 3;
            cp_async16(sB[stage] + r * PITCH + s * 16,
                       Bp + (size_t)(bn * BN + r) * Ktot + kcol + s * 8);
        }
    };

    issue(0, 0);
    CP_COMMIT();

    for (int kc = 0; kc < nkc; kc++) {
        const int buf = kc & 1;
        if (kc + 1 < nkc) {
            issue(buf ^ 1, kc + 1);
            CP_COMMIT();
            cp_wait<1>();
        } else {
            cp_wait<0>();
        }
        __syncthreads();

#pragma unroll
        for (int k16 = 0; k16 < 2; k16++) {
            uint32_t afr[MT16][4], bfr[NP][4];
#pragma unroll
            for (int mt = 0; mt < MT16; mt++) {
                int row = wm * MT + mt * 16 + a_row;
                ldsm_x4(afr[mt], sA[buf] + row * PITCH + (k16 * 2 + a_seg) * 16);
            }
#pragma unroll
            for (int np = 0; np < NP; np++) {
                int row = wn * NTT + np * 16 + b_row;
                ldsm_x4(bfr[np], sB[buf] + row * PITCH + (k16 * 2 + b_seg) * 16);
            }
#pragma unroll
            for (int mt = 0; mt < MT16; mt++)
#pragma unroll
                for (int np = 0; np < NP; np++) {
                    mma_bf16(acc[mt][2 * np + 0], afr[mt], bfr[np][0], bfr[np][1]);
                    mma_bf16(acc[mt][2 * np + 1], afr[mt], bfr[np][2], bfr[np][3]);
                }
        }
        __syncthreads();
    }

    const int r0 = zrow + bm * BM + wm * MT + (lane >> 2);
    const int c0 = bn * BN + wn * NTT + (lane & 3) * 2;
#pragma unroll
    for (int mt = 0; mt < MT16; mt++) {
#pragma unroll
        for (int nt = 0; nt < 4; nt++) {
            int row = r0 + mt * 16;
            int col = c0 + nt * 8;
            *(float2*)(C + (size_t)row * ldc + col) =
                make_float2(acc[mt][nt][0], acc[mt][nt][1]);
            *(float2*)(C + (size_t)(row + 8) * ldc + col) =
                make_float2(acc[mt][nt][2], acc[mt][nt][3]);
        }
    }
}

// ---------------------------------------------------------------------------
// out_proj reduce + residual + layer-1 rmsnorm, fused.  PO reads are streaming.
// ---------------------------------------------------------------------------
__global__ void __launch_bounds__(256)
reduce2rms_k(const float* __restrict__ P, const float* __restrict__ xin,
             const float* __restrict__ w,
             __nv_bfloat16* __restrict__ XNh, __nv_bfloat16* __restrict__ XNl,
             float* __restrict__ Xlast)
{
    int warp = threadIdx.x >> 5, lane = threadIdx.x & 31;
    size_t m = (size_t)blockIdx.x * 8 + warp;
    const float* p0 = P + m * DM;
    const float* p1 = P + (size_t)NT * DM + m * DM;
    const float* xr = xin + m * DM;

    float v[8];
    float ss = 0.f;
#pragma unroll
    for (int i = 0; i < 8; i++) {
        int j = lane + 32 * i;
        v[i] = xr[j] + __ldcs(&p0[j]) + __ldcs(&p1[j]);
        ss += v[i] * v[i];
    }
#pragma unroll
    for (int o = 16; o; o >>= 1) ss += __shfl_xor_sync(0xffffffffu, ss, o);
    float rs = rsqrtf(ss * (1.f / DM) + EPSF);

    bool last = ((m & (L_SZ - 1)) == (L_SZ - 1));
    int  bidx = (int)(m >> 10);
#pragma unroll
    for (int i = 0; i < 8; i++) {
        int j = lane + 32 * i;
        float y = v[i] * rs * w[j];
        __nv_bfloat16 hi, lo;
        split2(y, hi, lo);
        XNh[m * DM + j] = hi; XNl[m * DM + j] = lo;
        if (last) Xlast[(size_t)bidx * DM + j] = v[i];
    }
}

// ---------------------------------------------------------------------------
// fused x_proj reduce (4 slabs, streaming) + delta
// ---------------------------------------------------------------------------
__global__ void __launch_bounds__(256)
delta_fused_k(const float* __restrict__ PX, const float* __restrict__ dtw,
              const float* __restrict__ dtb, float* __restrict__ DBC,
              float* __restrict__ DELTA)
{
    __shared__ float sr[64][DR];
    const int tid = threadIdx.x;
    const size_t m0 = (size_t)blockIdx.x * 64;
    const int n4tot = NT * 16;

#pragma unroll
    for (int q = 0; q < 4; q++) {
        int f = tid + q * 256;
        int t = f >> 4, c4 = (f & 15);
        size_t o = (m0 + t) * 16 + c4;
        const float4* p = (const float4*)PX;
        float4 a = ldcs4(p + o), b = ldcs4(p + o + n4tot);
        float4 c = ldcs4(p + o + 2 * n4tot), d = ldcs4(p + o + 3 * n4tot);
        float4 r;
        r.x = (a.x + b.x) + (c.x + d.x);
        r.y = (a.y + b.y) + (c.y + d.y);
        r.z = (a.z + b.z) + (c.z + d.z);
        r.w = (a.w + b.w) + (c.w + d.w);
        ((float4*)DBC)[o] = r;
        if (c4 < 4) *(float4*)(&sr[t][c4 * 4]) = r;
    }
    __syncthreads();

    int d0 = tid, d1 = tid + 256;
    float wt0[DR], wt1[DR];
#pragma unroll
    for (int r = 0; r < DR; r++) {
        wt0[r] = dtw[r * DI + d0];
        wt1[r] = dtw[r * DI + d1];
    }
    float b0 = dtb[d0], b1 = dtb[d1];

#pragma unroll 4
    for (int t = 0; t < 64; t++) {
        float a0 = b0, a1 = b1;
#pragma unroll
        for (int r = 0; r < DR; r++) {
            float s = sr[t][r];
            a0 += s * wt0[r];
            a1 += s * wt1[r];
        }
        float sp0 = fmaxf(a0, 0.f) + __logf(1.f + __expf(-fabsf(a0)));
        float sp1 = fmaxf(a1, 0.f) + __logf(1.f + __expf(-fabsf(a1)));
        DELTA[(m0 + t) * DI + d0] = sp0;
        DELTA[(m0 + t) * DI + d1] = sp1;
    }
}

// ---------------------------------------------------------------------------
// causal depthwise conv (width 4) + bias + silu, CTT=16 (measured optimum)
// ---------------------------------------------------------------------------
__global__ void __launch_bounds__(128)
conv_silu_k(const float* __restrict__ XZ, const float* __restrict__ cw,
            const float* __restrict__ cb,
            __nv_bfloat16* __restrict__ XIh, __nv_bfloat16* __restrict__ XIl)
{
    int d  = blockIdx.x * 128 + threadIdx.x;
    int b  = blockIdx.z;
    int t0 = blockIdx.y * CTT;

    float w0 = cw[d * 4 + 0], w1 = cw[d * 4 + 1];
    float w2 = cw[d * 4 + 2], w3 = cw[d * 4 + 3];
    float bias = cb[d];

    const float* base = XZ + (size_t)b * L_SZ * (2 * DI) + d;

    float v[CTT + 3];
    v[0] = (t0 - 3 >= 0) ? base[(size_t)(t0 - 3) * (2 * DI)] : 0.f;
    v[1] = (t0 - 2 >= 0) ? base[(size_t)(t0 - 2) * (2 * DI)] : 0.f;
    v[2] = (t0 - 1 >= 0) ? base[(size_t)(t0 - 1) * (2 * DI)] : 0.f;
#pragma unroll
    for (int i = 0; i < CTT; i++)
        v[i + 3] = base[(size_t)(t0 + i) * (2 * DI)];

    size_t o = ((size_t)b * L_SZ + t0) * DI + d;
#pragma unroll
    for (int i = 0; i < CTT; i++) {
        float y = w0 * v[i] + w1 * v[i + 1] + w2 * v[i + 2] + w3 * v[i + 3] + bias;
        y = y / (1.f + __expf(-y));
        __nv_bfloat16 hi, lo;
        split2(y, hi, lo);
        XIh[o + (size_t)i * DI] = hi;
        XIl[o + (size_t)i * DI] = lo;
    }
}

// ---------------------------------------------------------------------------
// scan pass 1 (R13 body, PCS compression)
// ---------------------------------------------------------------------------
__global__ void __launch_bounds__(128)
scan1_k(const float* __restrict__ DELTA,
        const __nv_bfloat16* __restrict__ XIh, const __nv_bfloat16* __restrict__ XIl,
        const float* __restrict__ DBC, const float* __restrict__ alog,
        float* __restrict__ HC, float* __restrict__ PC, float* __restrict__ PCS)
{
    __shared__ float sB[CLEN][DS];
    int d = blockIdx.x * 128 + threadIdx.x;
    int c = blockIdx.y, b = blockIdx.z;
    size_t m0 = (size_t)b * L_SZ + (size_t)c * CLEN;

    for (int j = threadIdx.x; j < CLEN * DS; j += 128) {
        int i = j >> 4, n = j & 15;
        sB[i][n] = DBC[(m0 + i) * 64 + 16 + n];
    }

    float an[DS];
#pragma unroll
    for (int n = 0; n < DS; n++) an[n] = -__expf(alog[(size_t)d * DS + n]);
    float a0 = an[0];
    bool fast = true;
#pragma unroll
    for (int n = 1; n < DS; n++)
        if (fabsf(an[n] - a0 * (n + 1)) > 1e-4f * fabsf(an[n])) fast = false;
    __syncthreads();

    float h[DS];
#pragma unroll
    for (int n = 0; n < DS; n++) h[n] = 0.f;

    const float* dp = DELTA + m0 * DI + d;
    const __nv_bfloat16* uph = XIh + m0 * DI + d;
    const __nv_bfloat16* upl = XIl + m0 * DI + d;

    size_t o  = (((size_t)b * NCHUNK + c) * DI + d) * DS;
    size_t os = ((size_t)b * NCHUNK + c) * DI + d;

    if (fast) {
        float sdl = 0.f;
        for (int t = 0; t < CLEN; t++) {
            float dl = dp[(size_t)t * DI];
            float u  = __bfloat162float(uph[(size_t)t * DI])
                     + __bfloat162float(upl[(size_t)t * DI]);
            float du = dl * u;
            sdl += dl;
            float e1 = __expf(dl * a0);
            float pw[DS];
            pw[0] = e1;
            pw[1] = e1 * e1;
            pw[2] = pw[1] * e1;
            pw[3] = pw[1] * pw[1];
#pragma unroll
            for (int n = 4; n < DS; n++) pw[n] = pw[n - 4] * pw[3];
#pragma unroll
            for (int n = 0; n < DS; n++)
                h[n] = pw[n] * h[n] + du * sB[t][n];
        }
        PCS[os] = __expf(a0 * sdl);
    } else {
        float p[DS];
#pragma unroll
        for (int n = 0; n < DS; n++) p[n] = 1.f;
        for (int t = 0; t < CLEN; t++) {
            float dl = dp[(size_t)t * DI];
            float u  = __bfloat162float(uph[(size_t)t * DI])
                     + __bfloat162float(upl[(size_t)t * DI]);
            float du = dl * u;
#pragma unroll
            for (int n = 0; n < DS; n++) {
                float dA = __expf(dl * an[n]);
                h[n] = dA * h[n] + du * sB[t][n];
                p[n] *= dA;
            }
        }
#pragma unroll
        for (int n = 0; n < DS; n++) PC[o + n] = p[n];
        PCS[os] = __int_as_float(0x7fffffff);
    }

#pragma unroll
    for (int n = 0; n < DS; n++) HC[o + n] = h[n];
}

// ---------------------------------------------------------------------------
__global__ void __launch_bounds__(256)
combine_k(const float* __restrict__ HC, const float* __restrict__ PC,
          const float* __restrict__ PCS, float* __restrict__ HIN)
{
    int b = blockIdx.y;
    int idx = blockIdx.x * 256 + threadIdx.x;
    int d = idx >> 4, n = idx & 15;
    int m = n + 1;
    float hin = 0.f;
#pragma unroll 4
    for (int c = 0; c < NCHUNK; c++) {
        size_t base = ((size_t)b * NCHUNK + c) * DI;
        float es = PCS[base + d];
        float p;
        if (isnan(es)) {
            p = PC[(base + d) * DS + n];
        } else {
            float e2 = es * es, e4 = e2 * e2, e8 = e4 * e4;
            p = 1.f;
            if (m & 1)  p *= es;
            if (m & 2)  p *= e2;
            if (m & 4)  p *= e4;
            if (m & 8)  p *= e8;
            if (m & 16) p *= e8 * e8;
        }
        size_t o = (base + d) * DS + n;
        float hc = __ldcs(&HC[o]);
        HIN[o] = hin;
        hin = p * hin + hc;
    }
}

// ---------------------------------------------------------------------------
// scan pass 2 + gating.  LAST_ONLY skips y-dot except at the emitting step.
// ---------------------------------------------------------------------------
template<bool LAST_ONLY>
__global__ void __launch_bounds__(128)
scan2_k(const float* __restrict__ DELTA,
        const __nv_bfloat16* __restrict__ XIh, const __nv_bfloat16* __restrict__ XIl,
        const float* __restrict__ DBC, const float* __restrict__ alog,
        const float* __restrict__ dsk, const float* __restrict__ HIN,
        const float* __restrict__ XZ,
        __nv_bfloat16* __restrict__ YGh, __nv_bfloat16* __restrict__ YGl,
        float* __restrict__ YGF)
{
    __shared__ float sB[CLEN][DS];
    __shared__ float sC[CLEN][DS];
    int d = blockIdx.x * 128 + threadIdx.x;
    int c = LAST_ONLY ? (NCHUNK - 1) : blockIdx.y;
    int b = blockIdx.z;
    size_t m0 = (size_t)b * L_SZ + (size_t)c * CLEN;

    for (int j = threadIdx.x; j < CLEN * DS; j += 128) {
        int i = j >> 4, n = j & 15;
        sB[i][n] = DBC[(m0 + i) * 64 + 16 + n];
        sC[i][n] = DBC[(m0 + i) * 64 + 32 + n];
    }

    float an[DS];
#pragma unroll
    for (int n = 0; n < DS; n++) an[n] = -__expf(alog[(size_t)d * DS + n]);
    float a0 = an[0];
    bool fast = true;
#pragma unroll
    for (int n = 1; n < DS; n++)
        if (fabsf(an[n] - a0 * (n + 1)) > 1e-4f * fabsf(an[n])) fast = false;
    __syncthreads();

    float h[DS];
    size_t o = (((size_t)b * NCHUNK + c) * DI + d) * DS;
#pragma unroll
    for (int n = 0; n < DS; n++) h[n] = __ldcs(&HIN[o + n]);

    float Dd = dsk[d];
    const float* dp = DELTA + m0 * DI + d;
    const __nv_bfloat16* uph = XIh + m0 * DI + d;
    const __nv_bfloat16* upl = XIl + m0 * DI + d;
    const float* zp = XZ + m0 * (2 * DI) + DI + d;

    for (int t = 0; t < CLEN; t++) {
        float dl = dp[(size_t)t * DI];
        float u  = __bfloat162float(uph[(size_t)t * DI])
                 + __bfloat162float(upl[(size_t)t * DI]);
        float du = dl * u;
        float y0 = 0.f, y1 = 0.f, y2 = 0.f, y3 = 0.f;
        bool emit = !LAST_ONLY || (t == CLEN - 1);
        if (fast) {
            float e1 = __expf(dl * a0);
            float pw[DS];
            pw[0] = e1;
            pw[1] = e1 * e1;
            pw[2] = pw[1] * e1;
            pw[3] = pw[1] * pw[1];
#pragma unroll
            for (int n = 4; n < DS; n++) pw[n] = pw[n - 4] * pw[3];
            if (emit) {
#pragma unroll
                for (int n = 0; n < DS; n += 4) {
                    h[n + 0] = pw[n + 0] * h[n + 0] + du * sB[t][n + 0];
                    h[n + 1] = pw[n + 1] * h[n + 1] + du * sB[t][n + 1];
                    h[n + 2] = pw[n + 2] * h[n + 2] + du * sB[t][n + 2];
                    h[n + 3] = pw[n + 3] * h[n + 3] + du * sB[t][n + 3];
                    y0 += h[n + 0] * sC[t][n + 0];
                    y1 += h[n + 1] * sC[t][n + 1];
                    y2 += h[n + 2] * sC[t][n + 2];
                    y3 += h[n + 3] * sC[t][n + 3];
                }
            } else {
#pragma unroll
                for (int n = 0; n < DS; n++)
                    h[n] = pw[n] * h[n] + du * sB[t][n];
            }
        } else {
#pragma unroll
            for (int n = 0; n < DS; n++) {
                float dA = __expf(dl * an[n]);
                h[n] = dA * h[n] + du * sB[t][n];
                if (emit) y0 += h[n] * sC[t][n];
            }
        }
        if (emit) {
            float y = (y0 + y1) + (y2 + y3);
            float z = zp[(size_t)t * (2 * DI)];
            float g = z / (1.f + __expf(-z));
            float out = (y + u * Dd) * g;
            if (LAST_ONLY) {
                YGF[(size_t)b * DI + d] = out;
            } else {
                __nv_bfloat16 hi, lo;
                split2(out, hi, lo);
                YGh[m0 * DI + (size_t)t * DI + d] = hi;
                YGl[m0 * DI + (size_t)t * DI + d] = lo;
            }
        }
    }
}

// ---------------------------------------------------------------------------
__global__ void __launch_bounds__(256)
final2_k(const float* __restrict__ Xlast, const float* __restrict__ YGF,
         const float* __restrict__ opw1,
         const float* __restrict__ nfw, const float* __restrict__ fcw,
         const float* __restrict__ fcb, float* __restrict__ out)
{
    __shared__ float yg[DI];
    __shared__ float red[8];
    int b = blockIdx.x, n = threadIdx.x;
    int warp = n >> 5, lane = n & 31;

    for (int k = n; k < DI; k += 256) yg[k] = YGF[(size_t)b * DI + k];
    __syncthreads();

    float acc = 0.f;
#pragma unroll 4
    for (int k = 0; k < DI; k++)
        acc += yg[k] * opw1[(size_t)k * DM + n];

    float row = Xlast[(size_t)b * DM + n] + acc;

    float ss = row * row;
#pragma unroll
    for (int o = 16; o; o >>= 1) ss += __shfl_xor_sync(0xffffffffu, ss, o);
    if (lane == 0) red[warp] = ss;
    __syncthreads();
    if (warp == 0) {
        float v = (lane < 8) ? red[lane] : 0.f;
#pragma unroll
        for (int o = 4; o; o >>= 1) v += __shfl_xor_sync(0xffffffffu, v, o);
        if (lane == 0) red[0] = v;
    }
    __syncthreads();
    float rs = rsqrtf(red[0] * (1.f / DM) + EPSF);

    float part = row * rs * nfw[n] * fcw[n];
#pragma unroll
    for (int o = 16; o; o >>= 1) part += __shfl_xor_sync(0xffffffffu, part, o);
    __syncthreads();
    if (lane == 0) red[warp] = part;
    __syncthreads();
    if (n == 0) {
        float s = 0.f;
#pragma unroll
        for (int w = 0; w < 8; w++) s += red[w];
        out[b] = s + fcb[0];
    }
}

// ---------------------------------------------------------------------------
extern "C" void kernel_launch(void* const* d_in, const int* in_sizes, int n_in,
                              void* d_out, int out_size)
{
    (void)in_sizes; (void)n_in; (void)out_size;
    const float* x    = (const float*)d_in[0];
    const float* nw   = (const float*)d_in[1];
    const float* ipw  = (const float*)d_in[2];
    const float* cw   = (const float*)d_in[3];
    const float* cb   = (const float*)d_in[4];
    const float* xpw  = (const float*)d_in[5];
    const float* dtw  = (const float*)d_in[6];
    const float* dtb  = (const float*)d_in[7];
    const float* alog = (const float*)d_in[8];
    const float* dsk  = (const float*)d_in[9];
    const float* opw  = (const float*)d_in[10];
    const float* nfw  = (const float*)d_in[11];
    const float* fcw  = (const float*)d_in[12];
    const float* fcb  = (const float*)d_in[13];

    float *XZ, *DBC, *DELTA, *HC, *PC, *PCS, *HIN, *PX, *PO, *YGF, *XLAST;
    __nv_bfloat16 *XNh, *XNl, *XIh, *XIl, *YGh, *YGl;
    __nv_bfloat16 *Wih, *Wil, *Wxh, *Wxl, *Woh, *Wol;
    cudaGetSymbolAddress((void**)&XZ,    g_XZ);
    cudaGetSymbolAddress((void**)&DBC,   g_DBC);
    cudaGetSymbolAddress((void**)&DELTA, g_DELTA);
    cudaGetSymbolAddress((void**)&HC,    g_HC);
    cudaGetSymbolAddress((void**)&PC,    g_PC);
    cudaGetSymbolAddress((void**)&PCS,   g_PCS);
    cudaGetSymbolAddress((void**)&HIN,   g_HIN);
    cudaGetSymbolAddress((void**)&PX,    g_PX);
    cudaGetSymbolAddress((void**)&PO,    g_PO);
    cudaGetSymbolAddress((void**)&YGF,   g_YGF);
    cudaGetSymbolAddress((void**)&XLAST, g_XLAST);
    cudaGetSymbolAddress((void**)&XNh,   g_XNh);
    cudaGetSymbolAddress((void**)&XNl,   g_XNl);
    cudaGetSymbolAddress((void**)&XIh,   g_XIh);
    cudaGetSymbolAddress((void**)&XIl,   g_XIl);
    cudaGetSymbolAddress((void**)&YGh,   g_YGh);
    cudaGetSymbolAddress((void**)&YGl,   g_YGl);
    cudaGetSymbolAddress((void**)&Wih,   g_Wih);
    cudaGetSymbolAddress((void**)&Wil,   g_Wil);
    cudaGetSymbolAddress((void**)&Wxh,   g_Wxh);
    cudaGetSymbolAddress((void**)&Wxl,   g_Wxl);
    cudaGetSymbolAddress((void**)&Woh,   g_Woh);
    cudaGetSymbolAddress((void**)&Wol,   g_Wol);

    // slot 4 (ncu capture) = conv_silu_k (l=0): regression watch.
    rmsnorm_k<<<NT / 8, 256>>>(x, nw, XNh, XNl);                                   // 1
    repack_k<<<dim3(DM / 64, 1024 / 64, 2), 256>>>(ipw, Wih, Wil, DM, 2 * DI,      // 2
        (size_t)DM * 2 * DI, (size_t)1024 * DM);

    for (int l = 0; l < 2; l++) {
        mma_gemm_k<128, 128><<<dim3(2 * DI / 128, NT / 128, 1), 256>>>(            // 3 (l=0)
            XNh, XNl, Wih + (size_t)l * 1024 * DM, Wil + (size_t)l * 1024 * DM,
            XZ, DM, DM, 2 * DI);

        conv_silu_k<<<dim3(DI / 128, L_SZ / CTT, B_SZ), 128>>>(                    // 4 (l=0)
            XZ, cw + (size_t)l * DI * DCNV, cb + (size_t)l * DI, XIh, XIl);

        if (l == 0)
            repack_k<<<dim3(DI / 64, 1, 2), 256>>>(xpw, Wxh, Wxl, DI, 48,
                (size_t)DI * 48, (size_t)64 * DI);

        mma_gemm_k<64, 64><<<dim3(1, NT / 64, 4), 256>>>(
            XIh, XIl, Wxh + (size_t)l * 64 * DI, Wxl + (size_t)l * 64 * DI,
            PX, DI, DI / 4, 64);

        delta_fused_k<<<NT / 64, 256>>>(PX, dtw + (size_t)l * DR * DI,
                                        dtb + (size_t)l * DI, DBC, DELTA);

        scan1_k<<<dim3(DI / 128, NCHUNK, B_SZ), 128>>>(
            DELTA, XIh, XIl, DBC, alog + (size_t)l * DI * DS, HC, PC, PCS);

        combine_k<<<dim3((DI * DS) / 256, B_SZ), 256>>>(HC, PC, PCS, HIN);

        if (l == 0) {
            scan2_k<false><<<dim3(DI / 128, NCHUNK, B_SZ), 128>>>(
                DELTA, XIh, XIl, DBC, alog + (size_t)l * DI * DS,
                dsk + (size_t)l * DI, HIN, XZ, YGh, YGl, YGF);

            repack_k<<<dim3(DI / 64, DM / 64, 1), 256>>>(opw, Woh, Wol, DI, DM,
                (size_t)DI * DM, (size_t)DM * DI);

            mma_gemm_k<128, 128><<<dim3(DM / 128, NT / 128, 2), 256>>>(
                YGh, YGl, Woh, Wol, PO, DI, DI / 2, DM);

            reduce2rms_k<<<NT / 8, 256>>>(PO, x, nw + DM, XNh, XNl, XLAST);
        } else {
            scan2_k<true><<<dim3(DI / 128, 1, B_SZ), 128>>>(
                DELTA, XIh, XIl, DBC, alog + (size_t)l * DI * DS,
                dsk + (size_t)l * DI, HIN, XZ, YGh, YGl, YGF);

            final2_k<<<B_SZ, 256>>>(XLAST, YGF, opw + (size_t)1 * DI * DM,
                                    nfw, fcw, fcb, (float*)d_out);
        }
    }
}